// round 11
// baseline (speedup 1.0000x reference)
#include <cuda_runtime.h>
#include <cuda_bf16.h>
#include <math.h>

#define AN 50000
#define PN 100000
#define DIN 128
#define HD 256
#define CN 40
#define EN 300000

typedef unsigned short ushortx;

// fp32 state
__device__ float g_ha[(size_t)AN * HD];
__device__ float g_hp[(size_t)PN * HD];
__device__ float g_ta[(size_t)AN * HD];
__device__ float g_tp[(size_t)PN * HD];
__device__ float g_b01[2 * HD];
// bf16 hi/lo operand buffers
__device__ ushortx g_xah[(size_t)AN * DIN], g_xal[(size_t)AN * DIN];
__device__ ushortx g_xph[(size_t)PN * DIN], g_xpl[(size_t)PN * DIN];
__device__ ushortx g_hah[(size_t)AN * HD],  g_hal[(size_t)AN * HD];
__device__ ushortx g_hph[(size_t)PN * HD],  g_hpl[(size_t)PN * HD];
__device__ ushortx g_ag0h[(size_t)PN * HD], g_ag0l[(size_t)PN * HD];
__device__ ushortx g_ag1h[(size_t)PN * HD], g_ag1l[(size_t)PN * HD];
__device__ ushortx g_ag2h[(size_t)AN * HD], g_ag2l[(size_t)AN * HD];
// split weights, stacked segments (contiguous: dst index == linear j)
#define WOFF_EMBA 0
#define WOFF_EMBP (WOFF_EMBA + 128 * 256)
#define WOFF_WP0  (WOFF_EMBP + 128 * 256)
#define WOFF_WA0  (WOFF_WP0 + 768 * 256)
#define WOFF_WP1  (WOFF_WA0 + 512 * 256)
#define WOFF_WA1  (WOFF_WP1 + 768 * 256)
#define WOFF_P1A  (WOFF_WA1 + 512 * 256)
#define WOFF_P1P  (WOFF_P1A + 256 * 256)
#define WOFF_P2P  (WOFF_P1P + 256 * 256)
#define WTOT      (WOFF_P2P + 256 * 256)
__device__ ushortx g_wh[WTOT], g_wl[WTOT];
// CSR
#define NB_P 98                    // ceil(PN/1024)
#define NB_A 49                    // ceil(AN/1024)
#define NBT (NB_P + NB_P + NB_A)   // 245
__device__ int g_deg[3 * PN];
__device__ int g_off[3 * (PN + 1)];
__device__ int g_cur[3 * PN];
__device__ int g_perm[3 * EN];
__device__ int g_part[NBT];

// ---------------- helpers ----------------
__device__ __forceinline__ unsigned smem_u32(const void* p) {
    unsigned a;
    asm("{ .reg .u64 t; cvta.to.shared.u64 t, %1; cvt.u32.u64 %0, t; }" : "=r"(a) : "l"(p));
    return a;
}
__device__ __forceinline__ void cp16(unsigned dst, const void* src, int n) {
    asm volatile("cp.async.cg.shared.global [%0], [%1], 16, %2;" :: "r"(dst), "l"(src), "r"(n));
}
#define CP_COMMIT() asm volatile("cp.async.commit_group;" ::: "memory")
#define CP_WAIT1()  asm volatile("cp.async.wait_group 1;" ::: "memory")

__device__ __forceinline__ void bsplit(float x, float y, unsigned& h, unsigned& l) {
    __nv_bfloat162 hb = __floats2bfloat162_rn(x, y);
    float rx = x - __bfloat162float(hb.x);
    float ry = y - __bfloat162float(hb.y);
    __nv_bfloat162 lb = __floats2bfloat162_rn(rx, ry);
    h = *(unsigned*)&hb;
    l = *(unsigned*)&lb;
}
#define MMA16816(c, a, b) \
    asm volatile("mma.sync.aligned.m16n8k16.row.col.f32.bf16.bf16.f32 " \
        "{%0,%1,%2,%3},{%4,%5,%6,%7},{%8,%9},{%0,%1,%2,%3};" \
        : "+f"((c)[0]), "+f"((c)[1]), "+f"((c)[2]), "+f"((c)[3]) \
        : "r"((a)[0]), "r"((a)[1]), "r"((a)[2]), "r"((a)[3]), "r"((b)[0]), "r"((b)[1]))
#define LDSM4(r, addr) \
    asm volatile("ldmatrix.sync.aligned.m8n8.x4.shared.b16 {%0,%1,%2,%3},[%4];" \
        : "=r"((r)[0]), "=r"((r)[1]), "=r"((r)[2]), "=r"((r)[3]) : "r"(addr))
#define LDSM4T(r, addr) \
    asm volatile("ldmatrix.sync.aligned.m8n8.x4.trans.shared.b16 {%0,%1,%2,%3},[%4];" \
        : "=r"((r)[0]), "=r"((r)[1]), "=r"((r)[2]), "=r"((r)[3]) : "r"(addr))

__device__ __forceinline__ float warp_sum(float v) {
#pragma unroll
    for (int o = 16; o; o >>= 1) v += __shfl_xor_sync(0xffffffffu, v, o);
    return v;
}
__device__ __forceinline__ int warp_sumi(int v) {
#pragma unroll
    for (int o = 16; o; o >>= 1) v += __shfl_xor_sync(0xffffffffu, v, o);
    return v;
}
__device__ __forceinline__ float warp_max(float v) {
#pragma unroll
    for (int o = 16; o; o >>= 1) v = fmaxf(v, __shfl_xor_sync(0xffffffffu, v, o));
    return v;
}

// ---------------- one mega split kernel: x inputs, all weights, biases -----
#define NXA (AN * DIN)
#define NXP (PN * DIN)
#define NSPLIT_TOT (NXA + NXP + WTOT + 512)

__global__ void k_split_all(
    const float* __restrict__ x_author, const float* __restrict__ x_paper,
    const float* __restrict__ emb_W_author, const float* __restrict__ emb_W_paper,
    const float* __restrict__ W_self, const float* __restrict__ W_neigh,
    const float* __restrict__ pW1_author, const float* __restrict__ pW1_paper,
    const float* __restrict__ pW2_paper, const float* __restrict__ b_conv,
    ushortx* __restrict__ wh, ushortx* __restrict__ wl,
    ushortx* __restrict__ xah, ushortx* __restrict__ xal,
    ushortx* __restrict__ xph, ushortx* __restrict__ xpl,
    float* __restrict__ b01) {
    int i = blockIdx.x * blockDim.x + threadIdx.x;
    if (i >= NSPLIT_TOT) return;
    if (i < NXA) {
        float v = x_author[i];
        __nv_bfloat16 h = __float2bfloat16(v);
        xah[i] = *(ushortx*)&h;
        __nv_bfloat16 l = __float2bfloat16(v - __bfloat162float(h));
        xal[i] = *(ushortx*)&l;
        return;
    }
    i -= NXA;
    if (i < NXP) {
        float v = x_paper[i];
        __nv_bfloat16 h = __float2bfloat16(v);
        xph[i] = *(ushortx*)&h;
        __nv_bfloat16 l = __float2bfloat16(v - __bfloat162float(h));
        xpl[i] = *(ushortx*)&l;
        return;
    }
    i -= NXP;
    if (i < WTOT) {
        const int j = i;
        const int Q = 65536;  // 256*256
        float v;
        if (j < Q)               v = (j < Q / 2) ? emb_W_author[j] : emb_W_paper[j - Q / 2];
        else if (j < 2 * Q)      { int r = j - Q;     v = W_self[r] + W_self[Q + r]; }
        else if (j < 3 * Q)      v = W_neigh[j - 2 * Q];
        else if (j < 4 * Q)      v = W_neigh[Q + j - 3 * Q];
        else if (j < 5 * Q)      v = W_self[2 * Q + j - 4 * Q];
        else if (j < 6 * Q)      v = W_neigh[2 * Q + j - 5 * Q];
        else if (j < 7 * Q)      { int r = j - 6 * Q; v = W_self[3 * Q + r] + W_self[4 * Q + r]; }
        else if (j < 8 * Q)      v = W_neigh[3 * Q + j - 7 * Q];
        else if (j < 9 * Q)      v = W_neigh[4 * Q + j - 8 * Q];
        else if (j < 10 * Q)     v = W_self[5 * Q + j - 9 * Q];
        else if (j < 11 * Q)     v = W_neigh[5 * Q + j - 10 * Q];
        else if (j < 12 * Q)     v = pW1_author[j - 11 * Q];
        else if (j < 13 * Q)     v = pW1_paper[j - 12 * Q];
        else                     v = pW2_paper[j - 13 * Q];
        __nv_bfloat16 h = __float2bfloat16(v);
        wh[j] = *(ushortx*)&h;
        __nv_bfloat16 l = __float2bfloat16(v - __bfloat162float(h));
        wl[j] = *(ushortx*)&l;
        return;
    }
    i -= WTOT;  // i in [0,512): combined conv biases per layer
    int l = i >> 8, c = i & 255;
    b01[i] = b_conv[l * 768 + c] + b_conv[l * 768 + 256 + c];
}

// ---------------- CSR build ----------------
__global__ void k_zero3(int* __restrict__ deg) {
    int i = blockIdx.x * blockDim.x + threadIdx.x;
    if (i < 3 * PN) deg[i] = 0;
}
__global__ void k_hist3(const int* __restrict__ d0, const int* __restrict__ d1,
                        const int* __restrict__ d2, int* __restrict__ deg) {
    int i = blockIdx.x * blockDim.x + threadIdx.x;
    if (i >= 3 * EN) return;
    int t = i / EN, k = i - t * EN;
    const int* d = (t == 0) ? d0 : ((t == 1) ? d1 : d2);
    atomicAdd(&deg[t * PN + d[k]], 1);
}
__device__ __forceinline__ void scan_block_coords(int b, int& t, int& blk, int& nd) {
    if (b < NB_P)            { t = 0; blk = b;              nd = PN; }
    else if (b < 2 * NB_P)   { t = 1; blk = b - NB_P;       nd = PN; }
    else                     { t = 2; blk = b - 2 * NB_P;   nd = AN; }
}
__global__ void k_scan_sum(const int* __restrict__ deg, int* __restrict__ part) {
    __shared__ int sh[32];
    int t, blk, nd;
    scan_block_coords(blockIdx.x, t, blk, nd);
    int i = blk * 1024 + threadIdx.x;
    int v = (i < nd) ? deg[t * PN + i] : 0;
    v = warp_sumi(v);
    if ((threadIdx.x & 31) == 0) sh[threadIdx.x >> 5] = v;
    __syncthreads();
    if (threadIdx.x < 32) {
        int x = sh[threadIdx.x];
        x = warp_sumi(x);
        if (threadIdx.x == 0) part[blockIdx.x] = x;
    }
}
__global__ void k_scan_top(int* __restrict__ part, int* __restrict__ off) {
    int t = threadIdx.x;
    if (t >= 3) return;
    int base = (t == 0) ? 0 : ((t == 1) ? NB_P : 2 * NB_P);
    int n = (t == 2) ? NB_A : NB_P;
    int nd = (t == 2) ? AN : PN;
    int run = 0;
    for (int i = 0; i < n; ++i) { int v = part[base + i]; part[base + i] = run; run += v; }
    off[t * (PN + 1) + nd] = run;
}
__global__ void k_scan_apply(const int* __restrict__ deg, const int* __restrict__ part,
                             int* __restrict__ off, int* __restrict__ cur) {
    __shared__ int sh[1024];
    int t, blk, nd;
    scan_block_coords(blockIdx.x, t, blk, nd);
    int i = blk * 1024 + threadIdx.x;
    int v = (i < nd) ? deg[t * PN + i] : 0;
    sh[threadIdx.x] = v;
    __syncthreads();
#pragma unroll
    for (int d = 1; d < 1024; d <<= 1) {
        int x = (threadIdx.x >= d) ? sh[threadIdx.x - d] : 0;
        __syncthreads();
        sh[threadIdx.x] += x;
        __syncthreads();
    }
    if (i < nd) {
        int o = part[blockIdx.x] + sh[threadIdx.x] - v;  // exclusive
        off[t * (PN + 1) + i] = o;
        cur[t * PN + i] = o;
    }
}
__global__ void k_fill3(const int* __restrict__ s0, const int* __restrict__ d0,
                        const int* __restrict__ s1, const int* __restrict__ d1,
                        const int* __restrict__ s2, const int* __restrict__ d2,
                        int* __restrict__ cur, int* __restrict__ perm) {
    int i = blockIdx.x * blockDim.x + threadIdx.x;
    if (i >= 3 * EN) return;
    int t = i / EN, k = i - t * EN;
    const int* s = (t == 0) ? s0 : ((t == 1) ? s1 : s2);
    const int* d = (t == 0) ? d0 : ((t == 1) ? d1 : d2);
    int slot = atomicAdd(&cur[t * PN + d[k]], 1);
    perm[t * EN + slot] = s[k];
}

// ---------------- ALL 3 mean aggregations in one launch ----------------
// warps [0,PN)        : type0, src=ha  -> ag0
// warps [PN,2PN)      : type1, src=hp  -> ag1
// warps [2PN,2PN+AN)  : type2, src=hp  -> ag2
__global__ void k_agg3(const float* __restrict__ ha, const float* __restrict__ hp,
                       const int* __restrict__ off, const int* __restrict__ perm,
                       ushortx* __restrict__ ag0h, ushortx* __restrict__ ag0l,
                       ushortx* __restrict__ ag1h, ushortx* __restrict__ ag1l,
                       ushortx* __restrict__ ag2h, ushortx* __restrict__ ag2l) {
    int w = (blockIdx.x * blockDim.x + threadIdx.x) >> 5;
    int lane = threadIdx.x & 31;
    const float* h;
    const int* of;
    const int* pm;
    ushortx *oh, *ol;
    if (w < PN) {
        h = ha; of = off; pm = perm; oh = ag0h; ol = ag0l;
    } else if (w < 2 * PN) {
        w -= PN;
        h = hp; of = off + (PN + 1); pm = perm + EN; oh = ag1h; ol = ag1l;
    } else if (w < 2 * PN + AN) {
        w -= 2 * PN;
        h = hp; of = off + 2 * (PN + 1); pm = perm + 2 * EN; oh = ag2h; ol = ag2l;
    } else return;
    int s = of[w], e = of[w + 1];
    float4 a0 = make_float4(0.f, 0.f, 0.f, 0.f);
    float4 a1 = make_float4(0.f, 0.f, 0.f, 0.f);
    for (int i = s; i < e; ++i) {
        const float4* r = (const float4*)(h + (size_t)pm[i] * HD);
        float4 v0 = __ldg(&r[lane]);
        float4 v1 = __ldg(&r[lane + 32]);
        a0.x += v0.x; a0.y += v0.y; a0.z += v0.z; a0.w += v0.w;
        a1.x += v1.x; a1.y += v1.y; a1.z += v1.z; a1.w += v1.w;
    }
    float inv = (e > s) ? 1.f / (float)(e - s) : 0.f;
    a0.x *= inv; a0.y *= inv; a0.z *= inv; a0.w *= inv;
    a1.x *= inv; a1.y *= inv; a1.z *= inv; a1.w *= inv;
    unsigned h0, l0, h1, l1;
    unsigned* ohu = (unsigned*)(oh + (size_t)w * HD);
    unsigned* olu = (unsigned*)(ol + (size_t)w * HD);
    bsplit(a0.x, a0.y, h0, l0); bsplit(a0.z, a0.w, h1, l1);
    ohu[lane * 2] = h0; ohu[lane * 2 + 1] = h1;
    olu[lane * 2] = l0; olu[lane * 2 + 1] = l1;
    bsplit(a1.x, a1.y, h0, l0); bsplit(a1.z, a1.w, h1, l1);
    ohu[64 + lane * 2] = h0; ohu[64 + lane * 2 + 1] = h1;
    olu[64 + lane * 2] = l0; olu[64 + lane * 2 + 1] = l1;
}

// ---------------- bf16-input HMMA 3-split GEMM, 3-stage, occ=2, 1 sync/iter
#define A_ST 80
#define B_ST 272
#define OFF_AL 10240
#define OFF_BH 20480
#define OFF_BL 29184
#define STAGE 37888
#define NSTAGE 3

__global__ __launch_bounds__(256, 2) void k_bgemm(
    const ushortx* __restrict__ ah0, const ushortx* __restrict__ al0,
    const ushortx* __restrict__ ah1, const ushortx* __restrict__ al1,
    const ushortx* __restrict__ ah2, const ushortx* __restrict__ al2,
    const ushortx* __restrict__ Bh, const ushortx* __restrict__ Bl,
    const float* __restrict__ bias, float* __restrict__ C,
    ushortx* __restrict__ Ch, ushortx* __restrict__ Cl,
    int M, int N, int Ktot, int Kseg, int relu) {
    extern __shared__ char smc[];
    const int tid = threadIdx.x;
    const int lane = tid & 31;
    const int warp = tid >> 5;
    const int g = lane >> 2;
    const int t = lane & 3;
    const int wm = warp & 1;
    const int wn = warp >> 1;
    const int bm = blockIdx.y * 128;
    const int bn = blockIdx.x * 128;
    const unsigned sbase = smem_u32(smc);
    const int NIT = Ktot >> 5;
    const int segC = Kseg >> 5;

    float acc[4][4][4];
#pragma unroll
    for (int i = 0; i < 4; ++i)
#pragma unroll
        for (int j = 0; j < 4; ++j)
#pragma unroll
            for (int q = 0; q < 4; ++q) acc[i][j][q] = 0.f;

    const int ca = tid * 2;
    const int arow0 = ca >> 2, ac0 = ca & 3;
    const int arow1 = (ca + 1) >> 2, ac1 = (ca + 1) & 3;
    const int brow0 = ca >> 4, bc0 = ca & 15;
    const int brow1 = (ca + 1) >> 4, bc1 = (ca + 1) & 15;

    auto issue = [&](int it) {
        int seg = it / segC;
        int kloc = (it - seg * segC) << 5;
        const ushortx* pah = (seg == 0) ? ah0 : ((seg == 1) ? ah1 : ah2);
        const ushortx* pal = (seg == 0) ? al0 : ((seg == 1) ? al1 : al2);
        unsigned sa = sbase + (it % NSTAGE) * STAGE;
        int gr0 = bm + arow0, gr1 = bm + arow1;
        int ok0 = gr0 < M ? 16 : 0, ok1 = gr1 < M ? 16 : 0;
        size_t off0 = (size_t)(gr0 < M ? gr0 : 0) * Kseg + kloc + ac0 * 8;
        size_t off1 = (size_t)(gr1 < M ? gr1 : 0) * Kseg + kloc + ac1 * 8;
        cp16(sa + arow0 * A_ST + ac0 * 16, pah + off0, ok0);
        cp16(sa + arow1 * A_ST + ac1 * 16, pah + off1, ok1);
        cp16(sa + OFF_AL + arow0 * A_ST + ac0 * 16, pal + off0, ok0);
        cp16(sa + OFF_AL + arow1 * A_ST + ac1 * 16, pal + off1, ok1);
        int kg = it << 5;
        size_t bo0 = (size_t)(kg + brow0) * N + bn + bc0 * 8;
        size_t bo1 = (size_t)(kg + brow1) * N + bn + bc1 * 8;
        cp16(sa + OFF_BH + brow0 * B_ST + bc0 * 16, Bh + bo0, 16);
        cp16(sa + OFF_BH + brow1 * B_ST + bc1 * 16, Bh + bo1, 16);
        cp16(sa + OFF_BL + brow0 * B_ST + bc0 * 16, Bl + bo0, 16);
        cp16(sa + OFF_BL + brow1 * B_ST + bc1 * 16, Bl + bo1, 16);
        CP_COMMIT();
    };

    issue(0);
    issue(1);
    for (int it = 0; it < NIT; ++it) {
        CP_WAIT1();                 // group(it) done (one newer may be in flight)
        __syncthreads();            // all warps finished reading iter it-1's buf
        if (it + 2 < NIT) issue(it + 2);  // target buf (it+2)%3: free since it-1
        else CP_COMMIT();           // keep pending-group arithmetic consistent
        const unsigned sa = sbase + (it % NSTAGE) * STAGE;
#pragma unroll
        for (int kk = 0; kk < 2; ++kk) {
            unsigned ah[4][4], al[4][4], bh[2][4], bl[2][4];
            unsigned abase = sa + (wm * 64 + (lane & 15)) * A_ST + kk * 32 + ((lane >> 4) << 4);
#pragma unroll
            for (int i = 0; i < 4; ++i) {
                LDSM4(ah[i], abase + i * (16 * A_ST));
                LDSM4(al[i], abase + i * (16 * A_ST) + OFF_AL);
            }
            unsigned bbase = sa + OFF_BH + (kk * 16 + (lane & 15)) * B_ST +
                             (wn * 32 + ((lane >> 4) << 3)) * 2;
#pragma unroll
            for (int p = 0; p < 2; ++p) {
                LDSM4T(bh[p], bbase + p * 32);
                LDSM4T(bl[p], bbase + p * 32 + (OFF_BL - OFF_BH));
            }
#pragma unroll
            for (int i = 0; i < 4; ++i)
#pragma unroll
                for (int j = 0; j < 4; ++j) {
                    unsigned* bhj = &bh[j >> 1][(j & 1) * 2];
                    unsigned* blj = &bl[j >> 1][(j & 1) * 2];
                    MMA16816(acc[i][j], ah[i], bhj);
                    MMA16816(acc[i][j], ah[i], blj);
                    MMA16816(acc[i][j], al[i], bhj);
                }
        }
    }

#pragma unroll
    for (int i = 0; i < 4; ++i) {
        int r0 = bm + wm * 64 + i * 16 + g;
#pragma unroll
        for (int j = 0; j < 4; ++j) {
            int cn = bn + wn * 32 + j * 8 + 2 * t;
            float2 bv = make_float2(0.f, 0.f);
            if (bias) bv = *(const float2*)(bias + cn);
#pragma unroll
            for (int h = 0; h < 2; ++h) {
                int row = r0 + h * 8;
                if (row >= M) continue;
                float vx = acc[i][j][h * 2 + 0] + bv.x;
                float vy = acc[i][j][h * 2 + 1] + bv.y;
                if (relu) { vx = fmaxf(vx, 0.f); vy = fmaxf(vy, 0.f); }
                size_t o = (size_t)row * N + cn;
                if (C) *(float2*)(C + o) = make_float2(vx, vy);
                if (Ch) {
                    unsigned hh, ll;
                    bsplit(vx, vy, hh, ll);
                    *(unsigned*)(Ch + o) = hh;
                    *(unsigned*)(Cl + o) = ll;
                }
            }
        }
    }
}

// ---------------- fp32 SGEMM (N=40 head only) ----------------
#define BM 128
#define BN 64
#define BK 16
#define TM 8
#define TN 4
__global__ __launch_bounds__(256) void k_sgemm(
    const float* __restrict__ A, const float* __restrict__ B,
    const float* __restrict__ bias, float* __restrict__ C,
    int M, int N, int K) {
    __shared__ float As[BK][BM];
    __shared__ float Bs[BK][BN];
    const int tid = threadIdx.x;
    const int tx = tid & 15, ty = tid >> 4;
    const int bm = blockIdx.y * BM, bn = blockIdx.x * BN;
    float acc[TM][TN];
#pragma unroll
    for (int i = 0; i < TM; ++i)
#pragma unroll
        for (int j = 0; j < TN; ++j) acc[i][j] = 0.f;
    const int ar = tid >> 2, ac = (tid & 3) << 2;
    const int br = tid >> 4, bc = (tid & 15) << 2;
    for (int k0 = 0; k0 < K; k0 += BK) {
#pragma unroll
        for (int h = 0; h < 2; ++h) {
            int r = ar + h * 64, gr = bm + r;
            float4 v = make_float4(0.f, 0.f, 0.f, 0.f);
            if (gr < M) v = *(const float4*)(A + (size_t)gr * K + k0 + ac);
            As[ac + 0][r] = v.x; As[ac + 1][r] = v.y;
            As[ac + 2][r] = v.z; As[ac + 3][r] = v.w;
        }
        {
            int gc = bn + bc;
            float4 v = make_float4(0.f, 0.f, 0.f, 0.f);
            if (gc < N) v = *(const float4*)(B + (size_t)(k0 + br) * N + gc);
            *(float4*)&Bs[br][bc] = v;
        }
        __syncthreads();
#pragma unroll
        for (int kk = 0; kk < BK; ++kk) {
            float aF[TM], bF[TN];
#pragma unroll
            for (int i = 0; i < TM; ++i) aF[i] = As[kk][ty * TM + i];
#pragma unroll
            for (int j = 0; j < TN; ++j) bF[j] = Bs[kk][tx * TN + j];
#pragma unroll
            for (int i = 0; i < TM; ++i)
#pragma unroll
                for (int j = 0; j < TN; ++j) acc[i][j] = fmaf(aF[i], bF[j], acc[i][j]);
        }
        __syncthreads();
    }
    const int col = bn + tx * TN;
    if (col < N) {
        float4 bv = make_float4(0.f, 0.f, 0.f, 0.f);
        if (bias) bv = *(const float4*)(bias + col);
#pragma unroll
        for (int i = 0; i < TM; ++i) {
            int row = bm + ty * TM + i;
            if (row >= M) continue;
            *(float4*)(C + (size_t)row * N + col) =
                make_float4(acc[i][0] + bv.x, acc[i][1] + bv.y,
                            acc[i][2] + bv.z, acc[i][3] + bv.w);
        }
    }
}

// ---------------- fused relu+residual+LayerNorm + split, both node types ---
__global__ void k_ln2(const float* __restrict__ ta, float* __restrict__ ha,
                      ushortx* __restrict__ hah, ushortx* __restrict__ hal,
                      const float* __restrict__ ga_, const float* __restrict__ ba_,
                      const float* __restrict__ tp, float* __restrict__ hp,
                      ushortx* __restrict__ hph, ushortx* __restrict__ hpl,
                      const float* __restrict__ gp_, const float* __restrict__ bp_) {
    int w = (blockIdx.x * blockDim.x + threadIdx.x) >> 5;
    int lane = threadIdx.x & 31;
    const float* t;
    float* h;
    ushortx *hh, *hl;
    const float *g, *b;
    if (w < AN) {
        t = ta; h = ha; hh = hah; hl = hal; g = ga_; b = ba_;
    } else if (w < AN + PN) {
        w -= AN;
        t = tp; h = hp; hh = hph; hl = hpl; g = gp_; b = bp_;
    } else return;
    const float4* t4 = (const float4*)(t + (size_t)w * HD);
    float4* h4 = (float4*)(h + (size_t)w * HD);
    float4 x0 = t4[lane], x1 = t4[lane + 32];
    float4 p0 = h4[lane], p1 = h4[lane + 32];
    float u[8];
    u[0] = fmaxf(x0.x, 0.f) + p0.x; u[1] = fmaxf(x0.y, 0.f) + p0.y;
    u[2] = fmaxf(x0.z, 0.f) + p0.z; u[3] = fmaxf(x0.w, 0.f) + p0.w;
    u[4] = fmaxf(x1.x, 0.f) + p1.x; u[5] = fmaxf(x1.y, 0.f) + p1.y;
    u[6] = fmaxf(x1.z, 0.f) + p1.z; u[7] = fmaxf(x1.w, 0.f) + p1.w;
    float s = 0.f;
#pragma unroll
    for (int i = 0; i < 8; ++i) s += u[i];
    s = warp_sum(s);
    float mu = s * (1.f / HD);
    float v = 0.f;
#pragma unroll
    for (int i = 0; i < 8; ++i) { float d = u[i] - mu; v += d * d; }
    v = warp_sum(v);
    float rstd = rsqrtf(v * (1.f / HD) + 1e-5f);
    const float4* g4 = (const float4*)g;
    const float4* b4 = (const float4*)b;
    float4 ga = g4[lane], gb = g4[lane + 32];
    float4 ba = b4[lane], bb = b4[lane + 32];
    float o[8];
    o[0] = (u[0] - mu) * rstd * ga.x + ba.x; o[1] = (u[1] - mu) * rstd * ga.y + ba.y;
    o[2] = (u[2] - mu) * rstd * ga.z + ba.z; o[3] = (u[3] - mu) * rstd * ga.w + ba.w;
    o[4] = (u[4] - mu) * rstd * gb.x + bb.x; o[5] = (u[5] - mu) * rstd * gb.y + bb.y;
    o[6] = (u[6] - mu) * rstd * gb.z + bb.z; o[7] = (u[7] - mu) * rstd * gb.w + bb.w;
    h4[lane] = make_float4(o[0], o[1], o[2], o[3]);
    h4[lane + 32] = make_float4(o[4], o[5], o[6], o[7]);
    unsigned* hhu = (unsigned*)(hh + (size_t)w * HD);
    unsigned* hlu = (unsigned*)(hl + (size_t)w * HD);
    unsigned hv0, lv0, hv1, lv1;
    bsplit(o[0], o[1], hv0, lv0); bsplit(o[2], o[3], hv1, lv1);
    hhu[lane * 2] = hv0; hhu[lane * 2 + 1] = hv1;
    hlu[lane * 2] = lv0; hlu[lane * 2 + 1] = lv1;
    bsplit(o[4], o[5], hv0, lv0); bsplit(o[6], o[7], hv1, lv1);
    hhu[64 + lane * 2] = hv0; hhu[64 + lane * 2 + 1] = hv1;
    hlu[64 + lane * 2] = lv0; hlu[64 + lane * 2 + 1] = lv1;
}

__global__ void k_lsm(float* __restrict__ x, int rows) {
    int w = (blockIdx.x * blockDim.x + threadIdx.x) >> 5;
    int lane = threadIdx.x & 31;
    if (w >= rows) return;
    float* r = x + (size_t)w * CN;
    float v0 = r[lane];
    bool has1 = (lane + 32) < CN;
    float v1 = has1 ? r[lane + 32] : -3.4e38f;
    float m = warp_max(fmaxf(v0, v1));
    float s = expf(v0 - m) + (has1 ? expf(v1 - m) : 0.f);
    s = warp_sum(s);
    float lse = m + logf(s);
    r[lane] = v0 - lse;
    if (has1) r[lane + 32] = v1 - lse;
}

// ---------------- host ----------------
static inline void bgemm(const ushortx* ah0, const ushortx* al0,
                         const ushortx* ah1, const ushortx* al1,
                         const ushortx* ah2, const ushortx* al2,
                         const ushortx* Bh, const ushortx* Bl,
                         const float* bias, float* C, ushortx* Ch, ushortx* Cl,
                         int M, int N, int Ktot, int Kseg, int relu) {
    dim3 grid(N >> 7, (M + 127) >> 7);
    k_bgemm<<<grid, 256, NSTAGE * STAGE>>>(ah0, al0, ah1, al1, ah2, al2,
                                           Bh, Bl, bias, C, Ch, Cl,
                                           M, N, Ktot, Kseg, relu);
}

extern "C" void kernel_launch(void* const* d_in, const int* in_sizes, int n_in,
                              void* d_out, int out_size) {
    const float* x_author     = (const float*)d_in[0];
    const float* x_paper      = (const float*)d_in[1];
    const int*   e0_src       = (const int*)d_in[2];
    const int*   e0_dst       = (const int*)d_in[3];
    const int*   e1_src       = (const int*)d_in[4];
    const int*   e1_dst       = (const int*)d_in[5];
    const int*   e2_src       = (const int*)d_in[6];
    const int*   e2_dst       = (const int*)d_in[7];
    const float* emb_W_author = (const float*)d_in[8];
    const float* emb_b_author = (const float*)d_in[9];
    const float* emb_W_paper  = (const float*)d_in[10];
    const float* emb_b_paper  = (const float*)d_in[11];
    const float* W_self       = (const float*)d_in[12];
    const float* W_neigh      = (const float*)d_in[13];
    const float* b_conv       = (const float*)d_in[14];
    const float* ln_g_author  = (const float*)d_in[15];
    const float* ln_b_author  = (const float*)d_in[16];
    const float* ln_g_paper   = (const float*)d_in[17];
    const float* ln_b_paper   = (const float*)d_in[18];
    const float* pW1_author   = (const float*)d_in[19];
    const float* pb1_author   = (const float*)d_in[20];
    const float* pW2_author   = (const float*)d_in[21];
    const float* pb2_author   = (const float*)d_in[22];
    const float* pW1_paper    = (const float*)d_in[23];
    const float* pb1_paper    = (const float*)d_in[24];
    const float* pW2_paper    = (const float*)d_in[25];
    const float* pb2_paper    = (const float*)d_in[26];

    cudaFuncSetAttribute(k_bgemm, cudaFuncAttributeMaxDynamicSharedMemorySize, NSTAGE * STAGE);

    float *p_ha, *p_hp, *p_ta, *p_tp, *p_b01;
    ushortx *p_xah, *p_xal, *p_xph, *p_xpl, *p_hah, *p_hal, *p_hph, *p_hpl;
    ushortx *p_ag0h, *p_ag0l, *p_ag1h, *p_ag1l, *p_ag2h, *p_ag2l, *p_wh, *p_wl;
    int *p_deg, *p_off, *p_cur, *p_perm, *p_part;
    cudaGetSymbolAddress((void**)&p_ha, g_ha);
    cudaGetSymbolAddress((void**)&p_hp, g_hp);
    cudaGetSymbolAddress((void**)&p_ta, g_ta);
    cudaGetSymbolAddress((void**)&p_tp, g_tp);
    cudaGetSymbolAddress((void**)&p_b01, g_b01);
    cudaGetSymbolAddress((void**)&p_xah, g_xah);
    cudaGetSymbolAddress((void**)&p_xal, g_xal);
    cudaGetSymbolAddress((void**)&p_xph, g_xph);
    cudaGetSymbolAddress((void**)&p_xpl, g_xpl);
    cudaGetSymbolAddress((void**)&p_hah, g_hah);
    cudaGetSymbolAddress((void**)&p_hal, g_hal);
    cudaGetSymbolAddress((void**)&p_hph, g_hph);
    cudaGetSymbolAddress((void**)&p_hpl, g_hpl);
    cudaGetSymbolAddress((void**)&p_ag0h, g_ag0h);
    cudaGetSymbolAddress((void**)&p_ag0l, g_ag0l);
    cudaGetSymbolAddress((void**)&p_ag1h, g_ag1h);
    cudaGetSymbolAddress((void**)&p_ag1l, g_ag1l);
    cudaGetSymbolAddress((void**)&p_ag2h, g_ag2h);
    cudaGetSymbolAddress((void**)&p_ag2l, g_ag2l);
    cudaGetSymbolAddress((void**)&p_wh, g_wh);
    cudaGetSymbolAddress((void**)&p_wl, g_wl);
    cudaGetSymbolAddress((void**)&p_deg, g_deg);
    cudaGetSymbolAddress((void**)&p_off, g_off);
    cudaGetSymbolAddress((void**)&p_cur, g_cur);
    cudaGetSymbolAddress((void**)&p_perm, g_perm);
    cudaGetSymbolAddress((void**)&p_part, g_part);

    // ---- all input/weight/bias splits in ONE launch ----
    k_split_all<<<(NSPLIT_TOT + 255) / 256, 256>>>(
        x_author, x_paper, emb_W_author, emb_W_paper, W_self, W_neigh,
        pW1_author, pW1_paper, pW2_paper, b_conv,
        p_wh, p_wl, p_xah, p_xal, p_xph, p_xpl, p_b01);

    // ---- CSR build: zero, hist, 3-phase scan, fill ----
    k_zero3<<<(3 * PN + 255) / 256, 256>>>(p_deg);
    k_hist3<<<(3 * EN + 255) / 256, 256>>>(e0_dst, e1_dst, e2_dst, p_deg);
    k_scan_sum<<<NBT, 1024>>>(p_deg, p_part);
    k_scan_top<<<1, 32>>>(p_part, p_off);
    k_scan_apply<<<NBT, 1024>>>(p_deg, p_part, p_off, p_cur);
    k_fill3<<<(3 * EN + 255) / 256, 256>>>(e0_src, e0_dst, e1_src, e1_dst,
                                           e2_src, e2_dst, p_cur, p_perm);

    // ---- embeddings (fp32 h + split h) ----
    bgemm(p_xah, p_xal, 0, 0, 0, 0, p_wh + WOFF_EMBA, p_wl + WOFF_EMBA,
          emb_b_author, p_ha, p_hah, p_hal, AN, HD, DIN, DIN, 0);
    bgemm(p_xph, p_xpl, 0, 0, 0, 0, p_wh + WOFF_EMBP, p_wl + WOFF_EMBP,
          emb_b_paper, p_hp, p_hph, p_hpl, PN, HD, DIN, DIN, 0);

    // ---- 2 SAGE layers (4 launches per layer) ----
    const int WPO[2] = {WOFF_WP0, WOFF_WP1};
    const int WAO[2] = {WOFF_WA0, WOFF_WA1};
    const int NWARP_AGG = 2 * PN + AN;
    for (int l = 0; l < 2; ++l) {
        const float* bc = b_conv + (size_t)l * 3 * HD;
        k_agg3<<<(NWARP_AGG * 32 + 127) / 128, 128>>>(
            p_ha, p_hp, p_off, p_perm,
            p_ag0h, p_ag0l, p_ag1h, p_ag1l, p_ag2h, p_ag2l);
        bgemm(p_hph, p_hpl, p_ag0h, p_ag0l, p_ag1h, p_ag1l,
              p_wh + WPO[l], p_wl + WPO[l], p_b01 + l * HD,
              p_tp, 0, 0, PN, HD, 3 * HD, HD, 0);
        bgemm(p_hah, p_hal, p_ag2h, p_ag2l, 0, 0,
              p_wh + WAO[l], p_wl + WAO[l], bc + 2 * HD,
              p_ta, 0, 0, AN, HD, 2 * HD, HD, 0);
        k_ln2<<<((AN + PN) * 32 + 127) / 128, 128>>>(
            p_ta, p_ha, p_hah, p_hal, ln_g_author, ln_b_author,
            p_tp, p_hp, p_hph, p_hpl, ln_g_paper, ln_b_paper);
    }

    // ---- output heads ----
    float* out = (float*)d_out;
    bgemm(p_hah, p_hal, 0, 0, 0, 0, p_wh + WOFF_P1A, p_wl + WOFF_P1A,
          pb1_author, p_ta, 0, 0, AN, HD, HD, HD, 1);
    {
        dim3 grid((CN + BN - 1) / BN, (AN + BM - 1) / BM);
        k_sgemm<<<grid, 256>>>(p_ta, pW2_author, pb2_author, out, AN, CN, HD);
    }
    k_lsm<<<(AN * 32 + 127) / 128, 128>>>(out, AN);
    bgemm(p_hph, p_hpl, 0, 0, 0, 0, p_wh + WOFF_P1P, p_wl + WOFF_P1P,
          pb1_paper, 0, p_ag0h, p_ag0l, PN, HD, HD, HD, 1);
    bgemm(p_ag0h, p_ag0l, 0, 0, 0, 0, p_wh + WOFF_P2P, p_wl + WOFF_P2P,
          pb2_paper, out + (size_t)AN * CN, 0, 0, PN, HD, HD, HD, 0);
}

// round 12
// speedup vs baseline: 1.0110x; 1.0110x over previous
#include <cuda_runtime.h>
#include <cuda_bf16.h>
#include <math.h>

#define AN 50000
#define PN 100000
#define DIN 128
#define HD 256
#define CN 40
#define EN 300000

typedef unsigned short ushortx;

// fp32 state
__device__ float g_ha[(size_t)AN * HD];
__device__ float g_hp[(size_t)PN * HD];
__device__ float g_ta[(size_t)AN * HD];
__device__ float g_tp[(size_t)PN * HD];
__device__ float g_b01[2 * HD];
// bf16 hi/lo operand buffers
__device__ ushortx g_xah[(size_t)AN * DIN], g_xal[(size_t)AN * DIN];
__device__ ushortx g_xph[(size_t)PN * DIN], g_xpl[(size_t)PN * DIN];
__device__ ushortx g_hah[(size_t)AN * HD],  g_hal[(size_t)AN * HD];
__device__ ushortx g_hph[(size_t)PN * HD],  g_hpl[(size_t)PN * HD];
__device__ ushortx g_ag0h[(size_t)PN * HD], g_ag0l[(size_t)PN * HD];
__device__ ushortx g_ag1h[(size_t)PN * HD], g_ag1l[(size_t)PN * HD];
__device__ ushortx g_ag2h[(size_t)AN * HD], g_ag2l[(size_t)AN * HD];
// split weights, stacked segments (contiguous: dst index == linear j)
#define WOFF_EMBA 0
#define WOFF_EMBP (WOFF_EMBA + 128 * 256)
#define WOFF_WP0  (WOFF_EMBP + 128 * 256)
#define WOFF_WA0  (WOFF_WP0 + 768 * 256)
#define WOFF_WP1  (WOFF_WA0 + 512 * 256)
#define WOFF_WA1  (WOFF_WP1 + 768 * 256)
#define WOFF_P1A  (WOFF_WA1 + 512 * 256)
#define WOFF_P1P  (WOFF_P1A + 256 * 256)
#define WOFF_P2P  (WOFF_P1P + 256 * 256)
#define WTOT      (WOFF_P2P + 256 * 256)
__device__ ushortx g_wh[WTOT], g_wl[WTOT];
// CSR
#define NB_P 98                    // ceil(PN/1024)
#define NB_A 49                    // ceil(AN/1024)
#define NBT (NB_P + NB_P + NB_A)   // 245
__device__ int g_deg[3 * PN];
__device__ int g_off[3 * (PN + 1)];
__device__ int g_cur[3 * PN];
__device__ int g_perm[3 * EN];
__device__ int g_part[NBT];

// ---------------- helpers ----------------
__device__ __forceinline__ unsigned smem_u32(const void* p) {
    unsigned a;
    asm("{ .reg .u64 t; cvta.to.shared.u64 t, %1; cvt.u32.u64 %0, t; }" : "=r"(a) : "l"(p));
    return a;
}
__device__ __forceinline__ void cp16(unsigned dst, const void* src, int n) {
    asm volatile("cp.async.cg.shared.global [%0], [%1], 16, %2;" :: "r"(dst), "l"(src), "r"(n));
}
#define CP_COMMIT() asm volatile("cp.async.commit_group;" ::: "memory")
#define CP_WAIT0()  asm volatile("cp.async.wait_group 0;" ::: "memory")

__device__ __forceinline__ void bsplit(float x, float y, unsigned& h, unsigned& l) {
    __nv_bfloat162 hb = __floats2bfloat162_rn(x, y);
    float rx = x - __bfloat162float(hb.x);
    float ry = y - __bfloat162float(hb.y);
    __nv_bfloat162 lb = __floats2bfloat162_rn(rx, ry);
    h = *(unsigned*)&hb;
    l = *(unsigned*)&lb;
}
#define MMA16816(c, a, b) \
    asm volatile("mma.sync.aligned.m16n8k16.row.col.f32.bf16.bf16.f32 " \
        "{%0,%1,%2,%3},{%4,%5,%6,%7},{%8,%9},{%0,%1,%2,%3};" \
        : "+f"((c)[0]), "+f"((c)[1]), "+f"((c)[2]), "+f"((c)[3]) \
        : "r"((a)[0]), "r"((a)[1]), "r"((a)[2]), "r"((a)[3]), "r"((b)[0]), "r"((b)[1]))
#define LDSM4(r, addr) \
    asm volatile("ldmatrix.sync.aligned.m8n8.x4.shared.b16 {%0,%1,%2,%3},[%4];" \
        : "=r"((r)[0]), "=r"((r)[1]), "=r"((r)[2]), "=r"((r)[3]) : "r"(addr))
#define LDSM4T(r, addr) \
    asm volatile("ldmatrix.sync.aligned.m8n8.x4.trans.shared.b16 {%0,%1,%2,%3},[%4];" \
        : "=r"((r)[0]), "=r"((r)[1]), "=r"((r)[2]), "=r"((r)[3]) : "r"(addr))

__device__ __forceinline__ float warp_sum(float v) {
#pragma unroll
    for (int o = 16; o; o >>= 1) v += __shfl_xor_sync(0xffffffffu, v, o);
    return v;
}
__device__ __forceinline__ int warp_sumi(int v) {
#pragma unroll
    for (int o = 16; o; o >>= 1) v += __shfl_xor_sync(0xffffffffu, v, o);
    return v;
}
__device__ __forceinline__ float warp_max(float v) {
#pragma unroll
    for (int o = 16; o; o >>= 1) v = fmaxf(v, __shfl_xor_sync(0xffffffffu, v, o));
    return v;
}

// ---------------- one mega split kernel: x inputs, all weights, biases -----
#define NXA (AN * DIN)
#define NXP (PN * DIN)
#define NSPLIT_TOT (NXA + NXP + WTOT + 512)

__global__ void k_split_all(
    const float* __restrict__ x_author, const float* __restrict__ x_paper,
    const float* __restrict__ emb_W_author, const float* __restrict__ emb_W_paper,
    const float* __restrict__ W_self, const float* __restrict__ W_neigh,
    const float* __restrict__ pW1_author, const float* __restrict__ pW1_paper,
    const float* __restrict__ pW2_paper, const float* __restrict__ b_conv,
    ushortx* __restrict__ wh, ushortx* __restrict__ wl,
    ushortx* __restrict__ xah, ushortx* __restrict__ xal,
    ushortx* __restrict__ xph, ushortx* __restrict__ xpl,
    float* __restrict__ b01) {
    int i = blockIdx.x * blockDim.x + threadIdx.x;
    if (i >= NSPLIT_TOT) return;
    if (i < NXA) {
        float v = x_author[i];
        __nv_bfloat16 h = __float2bfloat16(v);
        xah[i] = *(ushortx*)&h;
        __nv_bfloat16 l = __float2bfloat16(v - __bfloat162float(h));
        xal[i] = *(ushortx*)&l;
        return;
    }
    i -= NXA;
    if (i < NXP) {
        float v = x_paper[i];
        __nv_bfloat16 h = __float2bfloat16(v);
        xph[i] = *(ushortx*)&h;
        __nv_bfloat16 l = __float2bfloat16(v - __bfloat162float(h));
        xpl[i] = *(ushortx*)&l;
        return;
    }
    i -= NXP;
    if (i < WTOT) {
        const int j = i;
        const int Q = 65536;  // 256*256
        float v;
        if (j < Q)               v = (j < Q / 2) ? emb_W_author[j] : emb_W_paper[j - Q / 2];
        else if (j < 2 * Q)      { int r = j - Q;     v = W_self[r] + W_self[Q + r]; }
        else if (j < 3 * Q)      v = W_neigh[j - 2 * Q];
        else if (j < 4 * Q)      v = W_neigh[Q + j - 3 * Q];
        else if (j < 5 * Q)      v = W_self[2 * Q + j - 4 * Q];
        else if (j < 6 * Q)      v = W_neigh[2 * Q + j - 5 * Q];
        else if (j < 7 * Q)      { int r = j - 6 * Q; v = W_self[3 * Q + r] + W_self[4 * Q + r]; }
        else if (j < 8 * Q)      v = W_neigh[3 * Q + j - 7 * Q];
        else if (j < 9 * Q)      v = W_neigh[4 * Q + j - 8 * Q];
        else if (j < 10 * Q)     v = W_self[5 * Q + j - 9 * Q];
        else if (j < 11 * Q)     v = W_neigh[5 * Q + j - 10 * Q];
        else if (j < 12 * Q)     v = pW1_author[j - 11 * Q];
        else if (j < 13 * Q)     v = pW1_paper[j - 12 * Q];
        else                     v = pW2_paper[j - 13 * Q];
        __nv_bfloat16 h = __float2bfloat16(v);
        wh[j] = *(ushortx*)&h;
        __nv_bfloat16 l = __float2bfloat16(v - __bfloat162float(h));
        wl[j] = *(ushortx*)&l;
        return;
    }
    i -= WTOT;  // i in [0,512): combined conv biases per layer
    int l = i >> 8, c = i & 255;
    b01[i] = b_conv[l * 768 + c] + b_conv[l * 768 + 256 + c];
}

// ---------------- CSR build ----------------
__global__ void k_zero3(int* __restrict__ deg) {
    int i = blockIdx.x * blockDim.x + threadIdx.x;
    if (i < 3 * PN) deg[i] = 0;
}
__global__ void k_hist3(const int* __restrict__ d0, const int* __restrict__ d1,
                        const int* __restrict__ d2, int* __restrict__ deg) {
    int i = blockIdx.x * blockDim.x + threadIdx.x;
    if (i >= 3 * EN) return;
    int t = i / EN, k = i - t * EN;
    const int* d = (t == 0) ? d0 : ((t == 1) ? d1 : d2);
    atomicAdd(&deg[t * PN + d[k]], 1);
}
__device__ __forceinline__ void scan_block_coords(int b, int& t, int& blk, int& nd) {
    if (b < NB_P)            { t = 0; blk = b;              nd = PN; }
    else if (b < 2 * NB_P)   { t = 1; blk = b - NB_P;       nd = PN; }
    else                     { t = 2; blk = b - 2 * NB_P;   nd = AN; }
}
__global__ void k_scan_sum(const int* __restrict__ deg, int* __restrict__ part) {
    __shared__ int sh[32];
    int t, blk, nd;
    scan_block_coords(blockIdx.x, t, blk, nd);
    int i = blk * 1024 + threadIdx.x;
    int v = (i < nd) ? deg[t * PN + i] : 0;
    v = warp_sumi(v);
    if ((threadIdx.x & 31) == 0) sh[threadIdx.x >> 5] = v;
    __syncthreads();
    if (threadIdx.x < 32) {
        int x = sh[threadIdx.x];
        x = warp_sumi(x);
        if (threadIdx.x == 0) part[blockIdx.x] = x;
    }
}
__global__ void k_scan_top(int* __restrict__ part, int* __restrict__ off) {
    int t = threadIdx.x;
    if (t >= 3) return;
    int base = (t == 0) ? 0 : ((t == 1) ? NB_P : 2 * NB_P);
    int n = (t == 2) ? NB_A : NB_P;
    int nd = (t == 2) ? AN : PN;
    int run = 0;
    for (int i = 0; i < n; ++i) { int v = part[base + i]; part[base + i] = run; run += v; }
    off[t * (PN + 1) + nd] = run;
}
__global__ void k_scan_apply(const int* __restrict__ deg, const int* __restrict__ part,
                             int* __restrict__ off, int* __restrict__ cur) {
    __shared__ int sh[1024];
    int t, blk, nd;
    scan_block_coords(blockIdx.x, t, blk, nd);
    int i = blk * 1024 + threadIdx.x;
    int v = (i < nd) ? deg[t * PN + i] : 0;
    sh[threadIdx.x] = v;
    __syncthreads();
#pragma unroll
    for (int d = 1; d < 1024; d <<= 1) {
        int x = (threadIdx.x >= d) ? sh[threadIdx.x - d] : 0;
        __syncthreads();
        sh[threadIdx.x] += x;
        __syncthreads();
    }
    if (i < nd) {
        int o = part[blockIdx.x] + sh[threadIdx.x] - v;  // exclusive
        off[t * (PN + 1) + i] = o;
        cur[t * PN + i] = o;
    }
}
__global__ void k_fill3(const int* __restrict__ s0, const int* __restrict__ d0,
                        const int* __restrict__ s1, const int* __restrict__ d1,
                        const int* __restrict__ s2, const int* __restrict__ d2,
                        int* __restrict__ cur, int* __restrict__ perm) {
    int i = blockIdx.x * blockDim.x + threadIdx.x;
    if (i >= 3 * EN) return;
    int t = i / EN, k = i - t * EN;
    const int* s = (t == 0) ? s0 : ((t == 1) ? s1 : s2);
    const int* d = (t == 0) ? d0 : ((t == 1) ? d1 : d2);
    int slot = atomicAdd(&cur[t * PN + d[k]], 1);
    perm[t * EN + slot] = s[k];
}

// ---------------- ALL 3 mean aggregations in one launch ----------------
__global__ void k_agg3(const float* __restrict__ ha, const float* __restrict__ hp,
                       const int* __restrict__ off, const int* __restrict__ perm,
                       ushortx* __restrict__ ag0h, ushortx* __restrict__ ag0l,
                       ushortx* __restrict__ ag1h, ushortx* __restrict__ ag1l,
                       ushortx* __restrict__ ag2h, ushortx* __restrict__ ag2l) {
    int w = (blockIdx.x * blockDim.x + threadIdx.x) >> 5;
    int lane = threadIdx.x & 31;
    const float* h;
    const int* of;
    const int* pm;
    ushortx *oh, *ol;
    if (w < PN) {
        h = ha; of = off; pm = perm; oh = ag0h; ol = ag0l;
    } else if (w < 2 * PN) {
        w -= PN;
        h = hp; of = off + (PN + 1); pm = perm + EN; oh = ag1h; ol = ag1l;
    } else if (w < 2 * PN + AN) {
        w -= 2 * PN;
        h = hp; of = off + 2 * (PN + 1); pm = perm + 2 * EN; oh = ag2h; ol = ag2l;
    } else return;
    int s = of[w], e = of[w + 1];
    float4 a0 = make_float4(0.f, 0.f, 0.f, 0.f);
    float4 a1 = make_float4(0.f, 0.f, 0.f, 0.f);
    for (int i = s; i < e; ++i) {
        const float4* r = (const float4*)(h + (size_t)pm[i] * HD);
        float4 v0 = __ldg(&r[lane]);
        float4 v1 = __ldg(&r[lane + 32]);
        a0.x += v0.x; a0.y += v0.y; a0.z += v0.z; a0.w += v0.w;
        a1.x += v1.x; a1.y += v1.y; a1.z += v1.z; a1.w += v1.w;
    }
    float inv = (e > s) ? 1.f / (float)(e - s) : 0.f;
    a0.x *= inv; a0.y *= inv; a0.z *= inv; a0.w *= inv;
    a1.x *= inv; a1.y *= inv; a1.z *= inv; a1.w *= inv;
    unsigned h0, l0, h1, l1;
    unsigned* ohu = (unsigned*)(oh + (size_t)w * HD);
    unsigned* olu = (unsigned*)(ol + (size_t)w * HD);
    bsplit(a0.x, a0.y, h0, l0); bsplit(a0.z, a0.w, h1, l1);
    ohu[lane * 2] = h0; ohu[lane * 2 + 1] = h1;
    olu[lane * 2] = l0; olu[lane * 2 + 1] = l1;
    bsplit(a1.x, a1.y, h0, l0); bsplit(a1.z, a1.w, h1, l1);
    ohu[64 + lane * 2] = h0; ohu[64 + lane * 2 + 1] = h1;
    olu[64 + lane * 2] = l0; olu[64 + lane * 2 + 1] = l1;
}

// ---------------- bf16-input HMMA 3-split GEMM, 2-stage, occ=2, 1 sync/iter
// (round-10 verified config: NSTAGE=2, issue-after-sync schedule)
#define A_ST 80
#define B_ST 272
#define OFF_AL 10240
#define OFF_BH 20480
#define OFF_BL 29184
#define STAGE 37888
#define NSTAGE 2

__global__ __launch_bounds__(256, 2) void k_bgemm(
    const ushortx* __restrict__ ah0, const ushortx* __restrict__ al0,
    const ushortx* __restrict__ ah1, const ushortx* __restrict__ al1,
    const ushortx* __restrict__ ah2, const ushortx* __restrict__ al2,
    const ushortx* __restrict__ Bh, const ushortx* __restrict__ Bl,
    const float* __restrict__ bias, float* __restrict__ C,
    ushortx* __restrict__ Ch, ushortx* __restrict__ Cl,
    int M, int N, int Ktot, int Kseg, int relu) {
    extern __shared__ char smc[];
    const int tid = threadIdx.x;
    const int lane = tid & 31;
    const int warp = tid >> 5;
    const int g = lane >> 2;
    const int t = lane & 3;
    const int wm = warp & 1;
    const int wn = warp >> 1;
    const int bm = blockIdx.y * 128;
    const int bn = blockIdx.x * 128;
    const unsigned sbase = smem_u32(smc);
    const int NIT = Ktot >> 5;
    const int segC = Kseg >> 5;

    float acc[4][4][4];
#pragma unroll
    for (int i = 0; i < 4; ++i)
#pragma unroll
        for (int j = 0; j < 4; ++j)
#pragma unroll
            for (int q = 0; q < 4; ++q) acc[i][j][q] = 0.f;

    const int ca = tid * 2;
    const int arow0 = ca >> 2, ac0 = ca & 3;
    const int arow1 = (ca + 1) >> 2, ac1 = (ca + 1) & 3;
    const int brow0 = ca >> 4, bc0 = ca & 15;
    const int brow1 = (ca + 1) >> 4, bc1 = (ca + 1) & 15;

    auto issue = [&](int it) {
        int seg = it / segC;
        int kloc = (it - seg * segC) << 5;
        const ushortx* pah = (seg == 0) ? ah0 : ((seg == 1) ? ah1 : ah2);
        const ushortx* pal = (seg == 0) ? al0 : ((seg == 1) ? al1 : al2);
        unsigned sa = sbase + (it & 1) * STAGE;
        int gr0 = bm + arow0, gr1 = bm + arow1;
        int ok0 = gr0 < M ? 16 : 0, ok1 = gr1 < M ? 16 : 0;
        size_t off0 = (size_t)(gr0 < M ? gr0 : 0) * Kseg + kloc + ac0 * 8;
        size_t off1 = (size_t)(gr1 < M ? gr1 : 0) * Kseg + kloc + ac1 * 8;
        cp16(sa + arow0 * A_ST + ac0 * 16, pah + off0, ok0);
        cp16(sa + arow1 * A_ST + ac1 * 16, pah + off1, ok1);
        cp16(sa + OFF_AL + arow0 * A_ST + ac0 * 16, pal + off0, ok0);
        cp16(sa + OFF_AL + arow1 * A_ST + ac1 * 16, pal + off1, ok1);
        int kg = it << 5;
        size_t bo0 = (size_t)(kg + brow0) * N + bn + bc0 * 8;
        size_t bo1 = (size_t)(kg + brow1) * N + bn + bc1 * 8;
        cp16(sa + OFF_BH + brow0 * B_ST + bc0 * 16, Bh + bo0, 16);
        cp16(sa + OFF_BH + brow1 * B_ST + bc1 * 16, Bh + bo1, 16);
        cp16(sa + OFF_BL + brow0 * B_ST + bc0 * 16, Bl + bo0, 16);
        cp16(sa + OFF_BL + brow1 * B_ST + bc1 * 16, Bl + bo1, 16);
        CP_COMMIT();
    };

    issue(0);
    for (int it = 0; it < NIT; ++it) {
        CP_WAIT0();                 // group(it) complete (only pending group)
        __syncthreads();            // all warps done reading buf^1 (iter it-1)
        if (it + 1 < NIT) issue(it + 1);  // overlaps compute of this iter
        const unsigned sa = sbase + (it & 1) * STAGE;
#pragma unroll
        for (int kk = 0; kk < 2; ++kk) {
            unsigned ah[4][4], al[4][4], bh[2][4], bl[2][4];
            unsigned abase = sa + (wm * 64 + (lane & 15)) * A_ST + kk * 32 + ((lane >> 4) << 4);
#pragma unroll
            for (int i = 0; i < 4; ++i) {
                LDSM4(ah[i], abase + i * (16 * A_ST));
                LDSM4(al[i], abase + i * (16 * A_ST) + OFF_AL);
            }
            unsigned bbase = sa + OFF_BH + (kk * 16 + (lane & 15)) * B_ST +
                             (wn * 32 + ((lane >> 4) << 3)) * 2;
#pragma unroll
            for (int p = 0; p < 2; ++p) {
                LDSM4T(bh[p], bbase + p * 32);
                LDSM4T(bl[p], bbase + p * 32 + (OFF_BL - OFF_BH));
            }
#pragma unroll
            for (int i = 0; i < 4; ++i)
#pragma unroll
                for (int j = 0; j < 4; ++j) {
                    unsigned* bhj = &bh[j >> 1][(j & 1) * 2];
                    unsigned* blj = &bl[j >> 1][(j & 1) * 2];
                    MMA16816(acc[i][j], ah[i], bhj);
                    MMA16816(acc[i][j], ah[i], blj);
                    MMA16816(acc[i][j], al[i], bhj);
                }
        }
    }

#pragma unroll
    for (int i = 0; i < 4; ++i) {
        int r0 = bm + wm * 64 + i * 16 + g;
#pragma unroll
        for (int j = 0; j < 4; ++j) {
            int cn = bn + wn * 32 + j * 8 + 2 * t;
            float2 bv = make_float2(0.f, 0.f);
            if (bias) bv = *(const float2*)(bias + cn);
#pragma unroll
            for (int h = 0; h < 2; ++h) {
                int row = r0 + h * 8;
                if (row >= M) continue;
                float vx = acc[i][j][h * 2 + 0] + bv.x;
                float vy = acc[i][j][h * 2 + 1] + bv.y;
                if (relu) { vx = fmaxf(vx, 0.f); vy = fmaxf(vy, 0.f); }
                size_t o = (size_t)row * N + cn;
                if (C) *(float2*)(C + o) = make_float2(vx, vy);
                if (Ch) {
                    unsigned hh, ll;
                    bsplit(vx, vy, hh, ll);
                    *(unsigned*)(Ch + o) = hh;
                    *(unsigned*)(Cl + o) = ll;
                }
            }
        }
    }
}

// ---------------- fp32 SGEMM (N=40 head only) ----------------
#define BM 128
#define BN 64
#define BK 16
#define TM 8
#define TN 4
__global__ __launch_bounds__(256) void k_sgemm(
    const float* __restrict__ A, const float* __restrict__ B,
    const float* __restrict__ bias, float* __restrict__ C,
    int M, int N, int K) {
    __shared__ float As[BK][BM];
    __shared__ float Bs[BK][BN];
    const int tid = threadIdx.x;
    const int tx = tid & 15, ty = tid >> 4;
    const int bm = blockIdx.y * BM, bn = blockIdx.x * BN;
    float acc[TM][TN];
#pragma unroll
    for (int i = 0; i < TM; ++i)
#pragma unroll
        for (int j = 0; j < TN; ++j) acc[i][j] = 0.f;
    const int ar = tid >> 2, ac = (tid & 3) << 2;
    const int br = tid >> 4, bc = (tid & 15) << 2;
    for (int k0 = 0; k0 < K; k0 += BK) {
#pragma unroll
        for (int h = 0; h < 2; ++h) {
            int r = ar + h * 64, gr = bm + r;
            float4 v = make_float4(0.f, 0.f, 0.f, 0.f);
            if (gr < M) v = *(const float4*)(A + (size_t)gr * K + k0 + ac);
            As[ac + 0][r] = v.x; As[ac + 1][r] = v.y;
            As[ac + 2][r] = v.z; As[ac + 3][r] = v.w;
        }
        {
            int gc = bn + bc;
            float4 v = make_float4(0.f, 0.f, 0.f, 0.f);
            if (gc < N) v = *(const float4*)(B + (size_t)(k0 + br) * N + gc);
            *(float4*)&Bs[br][bc] = v;
        }
        __syncthreads();
#pragma unroll
        for (int kk = 0; kk < BK; ++kk) {
            float aF[TM], bF[TN];
#pragma unroll
            for (int i = 0; i < TM; ++i) aF[i] = As[kk][ty * TM + i];
#pragma unroll
            for (int j = 0; j < TN; ++j) bF[j] = Bs[kk][tx * TN + j];
#pragma unroll
            for (int i = 0; i < TM; ++i)
#pragma unroll
                for (int j = 0; j < TN; ++j) acc[i][j] = fmaf(aF[i], bF[j], acc[i][j]);
        }
        __syncthreads();
    }
    const int col = bn + tx * TN;
    if (col < N) {
        float4 bv = make_float4(0.f, 0.f, 0.f, 0.f);
        if (bias) bv = *(const float4*)(bias + col);
#pragma unroll
        for (int i = 0; i < TM; ++i) {
            int row = bm + ty * TM + i;
            if (row >= M) continue;
            *(float4*)(C + (size_t)row * N + col) =
                make_float4(acc[i][0] + bv.x, acc[i][1] + bv.y,
                            acc[i][2] + bv.z, acc[i][3] + bv.w);
        }
    }
}

// ---------------- fused relu+residual+LayerNorm + split, both node types ---
__global__ void k_ln2(const float* __restrict__ ta, float* __restrict__ ha,
                      ushortx* __restrict__ hah, ushortx* __restrict__ hal,
                      const float* __restrict__ ga_, const float* __restrict__ ba_,
                      const float* __restrict__ tp, float* __restrict__ hp,
                      ushortx* __restrict__ hph, ushortx* __restrict__ hpl,
                      const float* __restrict__ gp_, const float* __restrict__ bp_) {
    int w = (blockIdx.x * blockDim.x + threadIdx.x) >> 5;
    int lane = threadIdx.x & 31;
    const float* t;
    float* h;
    ushortx *hh, *hl;
    const float *g, *b;
    if (w < AN) {
        t = ta; h = ha; hh = hah; hl = hal; g = ga_; b = ba_;
    } else if (w < AN + PN) {
        w -= AN;
        t = tp; h = hp; hh = hph; hl = hpl; g = gp_; b = bp_;
    } else return;
    const float4* t4 = (const float4*)(t + (size_t)w * HD);
    float4* h4 = (float4*)(h + (size_t)w * HD);
    float4 x0 = t4[lane], x1 = t4[lane + 32];
    float4 p0 = h4[lane], p1 = h4[lane + 32];
    float u[8];
    u[0] = fmaxf(x0.x, 0.f) + p0.x; u[1] = fmaxf(x0.y, 0.f) + p0.y;
    u[2] = fmaxf(x0.z, 0.f) + p0.z; u[3] = fmaxf(x0.w, 0.f) + p0.w;
    u[4] = fmaxf(x1.x, 0.f) + p1.x; u[5] = fmaxf(x1.y, 0.f) + p1.y;
    u[6] = fmaxf(x1.z, 0.f) + p1.z; u[7] = fmaxf(x1.w, 0.f) + p1.w;
    float s = 0.f;
#pragma unroll
    for (int i = 0; i < 8; ++i) s += u[i];
    s = warp_sum(s);
    float mu = s * (1.f / HD);
    float v = 0.f;
#pragma unroll
    for (int i = 0; i < 8; ++i) { float d = u[i] - mu; v += d * d; }
    v = warp_sum(v);
    float rstd = rsqrtf(v * (1.f / HD) + 1e-5f);
    const float4* g4 = (const float4*)g;
    const float4* b4 = (const float4*)b;
    float4 ga = g4[lane], gb = g4[lane + 32];
    float4 ba = b4[lane], bb = b4[lane + 32];
    float o[8];
    o[0] = (u[0] - mu) * rstd * ga.x + ba.x; o[1] = (u[1] - mu) * rstd * ga.y + ba.y;
    o[2] = (u[2] - mu) * rstd * ga.z + ba.z; o[3] = (u[3] - mu) * rstd * ga.w + ba.w;
    o[4] = (u[4] - mu) * rstd * gb.x + bb.x; o[5] = (u[5] - mu) * rstd * gb.y + bb.y;
    o[6] = (u[6] - mu) * rstd * gb.z + bb.z; o[7] = (u[7] - mu) * rstd * gb.w + bb.w;
    h4[lane] = make_float4(o[0], o[1], o[2], o[3]);
    h4[lane + 32] = make_float4(o[4], o[5], o[6], o[7]);
    unsigned* hhu = (unsigned*)(hh + (size_t)w * HD);
    unsigned* hlu = (unsigned*)(hl + (size_t)w * HD);
    unsigned hv0, lv0, hv1, lv1;
    bsplit(o[0], o[1], hv0, lv0); bsplit(o[2], o[3], hv1, lv1);
    hhu[lane * 2] = hv0; hhu[lane * 2 + 1] = hv1;
    hlu[lane * 2] = lv0; hlu[lane * 2 + 1] = lv1;
    bsplit(o[4], o[5], hv0, lv0); bsplit(o[6], o[7], hv1, lv1);
    hhu[64 + lane * 2] = hv0; hhu[64 + lane * 2 + 1] = hv1;
    hlu[64 + lane * 2] = lv0; hlu[64 + lane * 2 + 1] = lv1;
}

__global__ void k_lsm(float* __restrict__ x, int rows) {
    int w = (blockIdx.x * blockDim.x + threadIdx.x) >> 5;
    int lane = threadIdx.x & 31;
    if (w >= rows) return;
    float* r = x + (size_t)w * CN;
    float v0 = r[lane];
    bool has1 = (lane + 32) < CN;
    float v1 = has1 ? r[lane + 32] : -3.4e38f;
    float m = warp_max(fmaxf(v0, v1));
    float s = expf(v0 - m) + (has1 ? expf(v1 - m) : 0.f);
    s = warp_sum(s);
    float lse = m + logf(s);
    r[lane] = v0 - lse;
    if (has1) r[lane + 32] = v1 - lse;
}

// ---------------- host ----------------
static inline void bgemm(const ushortx* ah0, const ushortx* al0,
                         const ushortx* ah1, const ushortx* al1,
                         const ushortx* ah2, const ushortx* al2,
                         const ushortx* Bh, const ushortx* Bl,
                         const float* bias, float* C, ushortx* Ch, ushortx* Cl,
                         int M, int N, int Ktot, int Kseg, int relu) {
    dim3 grid(N >> 7, (M + 127) >> 7);
    k_bgemm<<<grid, 256, NSTAGE * STAGE>>>(ah0, al0, ah1, al1, ah2, al2,
                                           Bh, Bl, bias, C, Ch, Cl,
                                           M, N, Ktot, Kseg, relu);
}

extern "C" void kernel_launch(void* const* d_in, const int* in_sizes, int n_in,
                              void* d_out, int out_size) {
    const float* x_author     = (const float*)d_in[0];
    const float* x_paper      = (const float*)d_in[1];
    const int*   e0_src       = (const int*)d_in[2];
    const int*   e0_dst       = (const int*)d_in[3];
    const int*   e1_src       = (const int*)d_in[4];
    const int*   e1_dst       = (const int*)d_in[5];
    const int*   e2_src       = (const int*)d_in[6];
    const int*   e2_dst       = (const int*)d_in[7];
    const float* emb_W_author = (const float*)d_in[8];
    const float* emb_b_author = (const float*)d_in[9];
    const float* emb_W_paper  = (const float*)d_in[10];
    const float* emb_b_paper  = (const float*)d_in[11];
    const float* W_self       = (const float*)d_in[12];
    const float* W_neigh      = (const float*)d_in[13];
    const float* b_conv       = (const float*)d_in[14];
    const float* ln_g_author  = (const float*)d_in[15];
    const float* ln_b_author  = (const float*)d_in[16];
    const float* ln_g_paper   = (const float*)d_in[17];
    const float* ln_b_paper   = (const float*)d_in[18];
    const float* pW1_author   = (const float*)d_in[19];
    const float* pb1_author   = (const float*)d_in[20];
    const float* pW2_author   = (const float*)d_in[21];
    const float* pb2_author   = (const float*)d_in[22];
    const float* pW1_paper    = (const float*)d_in[23];
    const float* pb1_paper    = (const float*)d_in[24];
    const float* pW2_paper    = (const float*)d_in[25];
    const float* pb2_paper    = (const float*)d_in[26];

    cudaFuncSetAttribute(k_bgemm, cudaFuncAttributeMaxDynamicSharedMemorySize, NSTAGE * STAGE);

    float *p_ha, *p_hp, *p_ta, *p_tp, *p_b01;
    ushortx *p_xah, *p_xal, *p_xph, *p_xpl, *p_hah, *p_hal, *p_hph, *p_hpl;
    ushortx *p_ag0h, *p_ag0l, *p_ag1h, *p_ag1l, *p_ag2h, *p_ag2l, *p_wh, *p_wl;
    int *p_deg, *p_off, *p_cur, *p_perm, *p_part;
    cudaGetSymbolAddress((void**)&p_ha, g_ha);
    cudaGetSymbolAddress((void**)&p_hp, g_hp);
    cudaGetSymbolAddress((void**)&p_ta, g_ta);
    cudaGetSymbolAddress((void**)&p_tp, g_tp);
    cudaGetSymbolAddress((void**)&p_b01, g_b01);
    cudaGetSymbolAddress((void**)&p_xah, g_xah);
    cudaGetSymbolAddress((void**)&p_xal, g_xal);
    cudaGetSymbolAddress((void**)&p_xph, g_xph);
    cudaGetSymbolAddress((void**)&p_xpl, g_xpl);
    cudaGetSymbolAddress((void**)&p_hah, g_hah);
    cudaGetSymbolAddress((void**)&p_hal, g_hal);
    cudaGetSymbolAddress((void**)&p_hph, g_hph);
    cudaGetSymbolAddress((void**)&p_hpl, g_hpl);
    cudaGetSymbolAddress((void**)&p_ag0h, g_ag0h);
    cudaGetSymbolAddress((void**)&p_ag0l, g_ag0l);
    cudaGetSymbolAddress((void**)&p_ag1h, g_ag1h);
    cudaGetSymbolAddress((void**)&p_ag1l, g_ag1l);
    cudaGetSymbolAddress((void**)&p_ag2h, g_ag2h);
    cudaGetSymbolAddress((void**)&p_ag2l, g_ag2l);
    cudaGetSymbolAddress((void**)&p_wh, g_wh);
    cudaGetSymbolAddress((void**)&p_wl, g_wl);
    cudaGetSymbolAddress((void**)&p_deg, g_deg);
    cudaGetSymbolAddress((void**)&p_off, g_off);
    cudaGetSymbolAddress((void**)&p_cur, g_cur);
    cudaGetSymbolAddress((void**)&p_perm, g_perm);
    cudaGetSymbolAddress((void**)&p_part, g_part);

    // ---- all input/weight/bias splits in ONE launch ----
    k_split_all<<<(NSPLIT_TOT + 255) / 256, 256>>>(
        x_author, x_paper, emb_W_author, emb_W_paper, W_self, W_neigh,
        pW1_author, pW1_paper, pW2_paper, b_conv,
        p_wh, p_wl, p_xah, p_xal, p_xph, p_xpl, p_b01);

    // ---- CSR build: zero, hist, 3-phase scan, fill ----
    k_zero3<<<(3 * PN + 255) / 256, 256>>>(p_deg);
    k_hist3<<<(3 * EN + 255) / 256, 256>>>(e0_dst, e1_dst, e2_dst, p_deg);
    k_scan_sum<<<NBT, 1024>>>(p_deg, p_part);
    k_scan_top<<<1, 32>>>(p_part, p_off);
    k_scan_apply<<<NBT, 1024>>>(p_deg, p_part, p_off, p_cur);
    k_fill3<<<(3 * EN + 255) / 256, 256>>>(e0_src, e0_dst, e1_src, e1_dst,
                                           e2_src, e2_dst, p_cur, p_perm);

    // ---- embeddings (fp32 h + split h) ----
    bgemm(p_xah, p_xal, 0, 0, 0, 0, p_wh + WOFF_EMBA, p_wl + WOFF_EMBA,
          emb_b_author, p_ha, p_hah, p_hal, AN, HD, DIN, DIN, 0);
    bgemm(p_xph, p_xpl, 0, 0, 0, 0, p_wh + WOFF_EMBP, p_wl + WOFF_EMBP,
          emb_b_paper, p_hp, p_hph, p_hpl, PN, HD, DIN, DIN, 0);

    // ---- 2 SAGE layers (4 launches per layer) ----
    const int WPO[2] = {WOFF_WP0, WOFF_WP1};
    const int WAO[2] = {WOFF_WA0, WOFF_WA1};
    const int NWARP_AGG = 2 * PN + AN;
    for (int l = 0; l < 2; ++l) {
        const float* bc = b_conv + (size_t)l * 3 * HD;
        k_agg3<<<(NWARP_AGG * 32 + 127) / 128, 128>>>(
            p_ha, p_hp, p_off, p_perm,
            p_ag0h, p_ag0l, p_ag1h, p_ag1l, p_ag2h, p_ag2l);
        bgemm(p_hph, p_hpl, p_ag0h, p_ag0l, p_ag1h, p_ag1l,
              p_wh + WPO[l], p_wl + WPO[l], p_b01 + l * HD,
              p_tp, 0, 0, PN, HD, 3 * HD, HD, 0);
        bgemm(p_hah, p_hal, p_ag2h, p_ag2l, 0, 0,
              p_wh + WAO[l], p_wl + WAO[l], bc + 2 * HD,
              p_ta, 0, 0, AN, HD, 2 * HD, HD, 0);
        k_ln2<<<((AN + PN) * 32 + 127) / 128, 128>>>(
            p_ta, p_ha, p_hah, p_hal, ln_g_author, ln_b_author,
            p_tp, p_hp, p_hph, p_hpl, ln_g_paper, ln_b_paper);
    }

    // ---- output heads ----
    float* out = (float*)d_out;
    bgemm(p_hah, p_hal, 0, 0, 0, 0, p_wh + WOFF_P1A, p_wl + WOFF_P1A,
          pb1_author, p_ta, 0, 0, AN, HD, HD, HD, 1);
    {
        dim3 grid((CN + BN - 1) / BN, (AN + BM - 1) / BM);
        k_sgemm<<<grid, 256>>>(p_ta, pW2_author, pb2_author, out, AN, CN, HD);
    }
    k_lsm<<<(AN * 32 + 127) / 128, 128>>>(out, AN);
    bgemm(p_hph, p_hpl, 0, 0, 0, 0, p_wh + WOFF_P1P, p_wl + WOFF_P1P,
          pb1_paper, 0, p_ag0h, p_ag0l, PN, HD, HD, HD, 1);
    bgemm(p_ag0h, p_ag0l, 0, 0, 0, 0, p_wh + WOFF_P2P, p_wl + WOFF_P2P,
          pb2_paper, out + (size_t)AN * CN, 0, 0, PN, HD, HD, HD, 0);
}

// round 13
// speedup vs baseline: 1.0365x; 1.0252x over previous
#include <cuda_runtime.h>
#include <cuda_bf16.h>
#include <math.h>

#define AN 50000
#define PN 100000
#define DIN 128
#define HD 256
#define CN 40
#define EN 300000

typedef unsigned short ushortx;

// fp32 state
__device__ float g_ha[(size_t)AN * HD];
__device__ float g_hp[(size_t)PN * HD];
__device__ float g_ta[(size_t)AN * HD];
__device__ float g_tp[(size_t)PN * HD];
__device__ float g_b01[2 * HD];
// bf16 hi/lo operand buffers
__device__ ushortx g_xah[(size_t)AN * DIN], g_xal[(size_t)AN * DIN];
__device__ ushortx g_xph[(size_t)PN * DIN], g_xpl[(size_t)PN * DIN];
__device__ ushortx g_hah[(size_t)AN * HD],  g_hal[(size_t)AN * HD];
__device__ ushortx g_hph[(size_t)PN * HD],  g_hpl[(size_t)PN * HD];
__device__ ushortx g_ag0h[(size_t)PN * HD], g_ag0l[(size_t)PN * HD];
__device__ ushortx g_ag1h[(size_t)PN * HD], g_ag1l[(size_t)PN * HD];
__device__ ushortx g_ag2h[(size_t)AN * HD], g_ag2l[(size_t)AN * HD];
// split weights, stacked segments
#define WOFF_EMBA 0
#define WOFF_EMBP (WOFF_EMBA + 128 * 256)
#define WOFF_WP0  (WOFF_EMBP + 128 * 256)
#define WOFF_WA0  (WOFF_WP0 + 768 * 256)
#define WOFF_WP1  (WOFF_WA0 + 512 * 256)
#define WOFF_WA1  (WOFF_WP1 + 768 * 256)
#define WOFF_P1A  (WOFF_WA1 + 512 * 256)
#define WOFF_P1P  (WOFF_P1A + 256 * 256)
#define WOFF_P2P  (WOFF_P1P + 256 * 256)
#define WTOT      (WOFF_P2P + 256 * 256)
__device__ ushortx g_wh[WTOT], g_wl[WTOT];
// CSR
#define NB_P 98
#define NB_A 49
#define NBT (NB_P + NB_P + NB_A)
__device__ int g_deg[3 * PN];
__device__ int g_off[3 * (PN + 1)];
__device__ int g_cur[3 * PN];
__device__ int g_perm[3 * EN];
__device__ int g_part[NBT];

// ---------------- helpers ----------------
__device__ __forceinline__ unsigned smem_u32(const void* p) {
    unsigned a;
    asm("{ .reg .u64 t; cvta.to.shared.u64 t, %1; cvt.u32.u64 %0, t; }" : "=r"(a) : "l"(p));
    return a;
}
__device__ __forceinline__ void cp16(unsigned dst, const void* src, int n) {
    asm volatile("cp.async.cg.shared.global [%0], [%1], 16, %2;" :: "r"(dst), "l"(src), "r"(n));
}
#define CP_COMMIT() asm volatile("cp.async.commit_group;" ::: "memory")
#define CP_WAIT0()  asm volatile("cp.async.wait_group 0;" ::: "memory")

__device__ __forceinline__ void bsplit(float x, float y, unsigned& h, unsigned& l) {
    __nv_bfloat162 hb = __floats2bfloat162_rn(x, y);
    float rx = x - __bfloat162float(hb.x);
    float ry = y - __bfloat162float(hb.y);
    __nv_bfloat162 lb = __floats2bfloat162_rn(rx, ry);
    h = *(unsigned*)&hb;
    l = *(unsigned*)&lb;
}
#define MMA16816(c, a, b) \
    asm volatile("mma.sync.aligned.m16n8k16.row.col.f32.bf16.bf16.f32 " \
        "{%0,%1,%2,%3},{%4,%5,%6,%7},{%8,%9},{%0,%1,%2,%3};" \
        : "+f"((c)[0]), "+f"((c)[1]), "+f"((c)[2]), "+f"((c)[3]) \
        : "r"((a)[0]), "r"((a)[1]), "r"((a)[2]), "r"((a)[3]), "r"((b)[0]), "r"((b)[1]))
#define LDSM4(r, addr) \
    asm volatile("ldmatrix.sync.aligned.m8n8.x4.shared.b16 {%0,%1,%2,%3},[%4];" \
        : "=r"((r)[0]), "=r"((r)[1]), "=r"((r)[2]), "=r"((r)[3]) : "r"(addr))
#define LDSM4T(r, addr) \
    asm volatile("ldmatrix.sync.aligned.m8n8.x4.trans.shared.b16 {%0,%1,%2,%3},[%4];" \
        : "=r"((r)[0]), "=r"((r)[1]), "=r"((r)[2]), "=r"((r)[3]) : "r"(addr))

__device__ __forceinline__ float warp_sum(float v) {
#pragma unroll
    for (int o = 16; o; o >>= 1) v += __shfl_xor_sync(0xffffffffu, v, o);
    return v;
}
__device__ __forceinline__ int warp_sumi(int v) {
#pragma unroll
    for (int o = 16; o; o >>= 1) v += __shfl_xor_sync(0xffffffffu, v, o);
    return v;
}
__device__ __forceinline__ float warp_max(float v) {
#pragma unroll
    for (int o = 16; o; o >>= 1) v = fmaxf(v, __shfl_xor_sync(0xffffffffu, v, o));
    return v;
}

// ---------------- one mega split kernel ----------------
#define NXA (AN * DIN)
#define NXP (PN * DIN)
#define NSPLIT_TOT (NXA + NXP + WTOT + 512)

__global__ void k_split_all(
    const float* __restrict__ x_author, const float* __restrict__ x_paper,
    const float* __restrict__ emb_W_author, const float* __restrict__ emb_W_paper,
    const float* __restrict__ W_self, const float* __restrict__ W_neigh,
    const float* __restrict__ pW1_author, const float* __restrict__ pW1_paper,
    const float* __restrict__ pW2_paper, const float* __restrict__ b_conv,
    ushortx* __restrict__ wh, ushortx* __restrict__ wl,
    ushortx* __restrict__ xah, ushortx* __restrict__ xal,
    ushortx* __restrict__ xph, ushortx* __restrict__ xpl,
    float* __restrict__ b01) {
    int i = blockIdx.x * blockDim.x + threadIdx.x;
    if (i >= NSPLIT_TOT) return;
    if (i < NXA) {
        float v = x_author[i];
        __nv_bfloat16 h = __float2bfloat16(v);
        xah[i] = *(ushortx*)&h;
        __nv_bfloat16 l = __float2bfloat16(v - __bfloat162float(h));
        xal[i] = *(ushortx*)&l;
        return;
    }
    i -= NXA;
    if (i < NXP) {
        float v = x_paper[i];
        __nv_bfloat16 h = __float2bfloat16(v);
        xph[i] = *(ushortx*)&h;
        __nv_bfloat16 l = __float2bfloat16(v - __bfloat162float(h));
        xpl[i] = *(ushortx*)&l;
        return;
    }
    i -= NXP;
    if (i < WTOT) {
        const int j = i;
        const int Q = 65536;
        float v;
        if (j < Q)               v = (j < Q / 2) ? emb_W_author[j] : emb_W_paper[j - Q / 2];
        else if (j < 2 * Q)      { int r = j - Q;     v = W_self[r] + W_self[Q + r]; }
        else if (j < 3 * Q)      v = W_neigh[j - 2 * Q];
        else if (j < 4 * Q)      v = W_neigh[Q + j - 3 * Q];
        else if (j < 5 * Q)      v = W_self[2 * Q + j - 4 * Q];
        else if (j < 6 * Q)      v = W_neigh[2 * Q + j - 5 * Q];
        else if (j < 7 * Q)      { int r = j - 6 * Q; v = W_self[3 * Q + r] + W_self[4 * Q + r]; }
        else if (j < 8 * Q)      v = W_neigh[3 * Q + j - 7 * Q];
        else if (j < 9 * Q)      v = W_neigh[4 * Q + j - 8 * Q];
        else if (j < 10 * Q)     v = W_self[5 * Q + j - 9 * Q];
        else if (j < 11 * Q)     v = W_neigh[5 * Q + j - 10 * Q];
        else if (j < 12 * Q)     v = pW1_author[j - 11 * Q];
        else if (j < 13 * Q)     v = pW1_paper[j - 12 * Q];
        else                     v = pW2_paper[j - 13 * Q];
        __nv_bfloat16 h = __float2bfloat16(v);
        wh[j] = *(ushortx*)&h;
        __nv_bfloat16 l = __float2bfloat16(v - __bfloat162float(h));
        wl[j] = *(ushortx*)&l;
        return;
    }
    i -= WTOT;
    int l = i >> 8, c = i & 255;
    b01[i] = b_conv[l * 768 + c] + b_conv[l * 768 + 256 + c];
}

// ---------------- CSR build ----------------
__global__ void k_zero3(int* __restrict__ deg) {
    int i = blockIdx.x * blockDim.x + threadIdx.x;
    if (i < 3 * PN) deg[i] = 0;
}
__global__ void k_hist3(const int* __restrict__ d0, const int* __restrict__ d1,
                        const int* __restrict__ d2, int* __restrict__ deg) {
    int i = blockIdx.x * blockDim.x + threadIdx.x;
    if (i >= 3 * EN) return;
    int t = i / EN, k = i - t * EN;
    const int* d = (t == 0) ? d0 : ((t == 1) ? d1 : d2);
    atomicAdd(&deg[t * PN + d[k]], 1);
}
__device__ __forceinline__ void scan_block_coords(int b, int& t, int& blk, int& nd) {
    if (b < NB_P)            { t = 0; blk = b;              nd = PN; }
    else if (b < 2 * NB_P)   { t = 1; blk = b - NB_P;       nd = PN; }
    else                     { t = 2; blk = b - 2 * NB_P;   nd = AN; }
}
__global__ void k_scan_sum(const int* __restrict__ deg, int* __restrict__ part) {
    __shared__ int sh[32];
    int t, blk, nd;
    scan_block_coords(blockIdx.x, t, blk, nd);
    int i = blk * 1024 + threadIdx.x;
    int v = (i < nd) ? deg[t * PN + i] : 0;
    v = warp_sumi(v);
    if ((threadIdx.x & 31) == 0) sh[threadIdx.x >> 5] = v;
    __syncthreads();
    if (threadIdx.x < 32) {
        int x = sh[threadIdx.x];
        x = warp_sumi(x);
        if (threadIdx.x == 0) part[blockIdx.x] = x;
    }
}
__global__ void k_scan_top(int* __restrict__ part, int* __restrict__ off) {
    int t = threadIdx.x;
    if (t >= 3) return;
    int base = (t == 0) ? 0 : ((t == 1) ? NB_P : 2 * NB_P);
    int n = (t == 2) ? NB_A : NB_P;
    int nd = (t == 2) ? AN : PN;
    int run = 0;
    for (int i = 0; i < n; ++i) { int v = part[base + i]; part[base + i] = run; run += v; }
    off[t * (PN + 1) + nd] = run;
}
__global__ void k_scan_apply(const int* __restrict__ deg, const int* __restrict__ part,
                             int* __restrict__ off, int* __restrict__ cur) {
    __shared__ int sh[1024];
    int t, blk, nd;
    scan_block_coords(blockIdx.x, t, blk, nd);
    int i = blk * 1024 + threadIdx.x;
    int v = (i < nd) ? deg[t * PN + i] : 0;
    sh[threadIdx.x] = v;
    __syncthreads();
#pragma unroll
    for (int d = 1; d < 1024; d <<= 1) {
        int x = (threadIdx.x >= d) ? sh[threadIdx.x - d] : 0;
        __syncthreads();
        sh[threadIdx.x] += x;
        __syncthreads();
    }
    if (i < nd) {
        int o = part[blockIdx.x] + sh[threadIdx.x] - v;
        off[t * (PN + 1) + i] = o;
        cur[t * PN + i] = o;
    }
}
__global__ void k_fill3(const int* __restrict__ s0, const int* __restrict__ d0,
                        const int* __restrict__ s1, const int* __restrict__ d1,
                        const int* __restrict__ s2, const int* __restrict__ d2,
                        int* __restrict__ cur, int* __restrict__ perm) {
    int i = blockIdx.x * blockDim.x + threadIdx.x;
    if (i >= 3 * EN) return;
    int t = i / EN, k = i - t * EN;
    const int* s = (t == 0) ? s0 : ((t == 1) ? s1 : s2);
    const int* d = (t == 0) ? d0 : ((t == 1) ? d1 : d2);
    int slot = atomicAdd(&cur[t * PN + d[k]], 1);
    perm[t * EN + slot] = s[k];
}

// ---------------- ALL 3 mean aggregations in one launch ----------------
__global__ void k_agg3(const float* __restrict__ ha, const float* __restrict__ hp,
                       const int* __restrict__ off, const int* __restrict__ perm,
                       ushortx* __restrict__ ag0h, ushortx* __restrict__ ag0l,
                       ushortx* __restrict__ ag1h, ushortx* __restrict__ ag1l,
                       ushortx* __restrict__ ag2h, ushortx* __restrict__ ag2l) {
    int w = (blockIdx.x * blockDim.x + threadIdx.x) >> 5;
    int lane = threadIdx.x & 31;
    const float* h;
    const int* of;
    const int* pm;
    ushortx *oh, *ol;
    if (w < PN) {
        h = ha; of = off; pm = perm; oh = ag0h; ol = ag0l;
    } else if (w < 2 * PN) {
        w -= PN;
        h = hp; of = off + (PN + 1); pm = perm + EN; oh = ag1h; ol = ag1l;
    } else if (w < 2 * PN + AN) {
        w -= 2 * PN;
        h = hp; of = off + 2 * (PN + 1); pm = perm + 2 * EN; oh = ag2h; ol = ag2l;
    } else return;
    int s = of[w], e = of[w + 1];
    float4 a0 = make_float4(0.f, 0.f, 0.f, 0.f);
    float4 a1 = make_float4(0.f, 0.f, 0.f, 0.f);
    for (int i = s; i < e; ++i) {
        const float4* r = (const float4*)(h + (size_t)pm[i] * HD);
        float4 v0 = __ldg(&r[lane]);
        float4 v1 = __ldg(&r[lane + 32]);
        a0.x += v0.x; a0.y += v0.y; a0.z += v0.z; a0.w += v0.w;
        a1.x += v1.x; a1.y += v1.y; a1.z += v1.z; a1.w += v1.w;
    }
    float inv = (e > s) ? 1.f / (float)(e - s) : 0.f;
    a0.x *= inv; a0.y *= inv; a0.z *= inv; a0.w *= inv;
    a1.x *= inv; a1.y *= inv; a1.z *= inv; a1.w *= inv;
    unsigned h0, l0, h1, l1;
    unsigned* ohu = (unsigned*)(oh + (size_t)w * HD);
    unsigned* olu = (unsigned*)(ol + (size_t)w * HD);
    bsplit(a0.x, a0.y, h0, l0); bsplit(a0.z, a0.w, h1, l1);
    ohu[lane * 2] = h0; ohu[lane * 2 + 1] = h1;
    olu[lane * 2] = l0; olu[lane * 2 + 1] = l1;
    bsplit(a1.x, a1.y, h0, l0); bsplit(a1.z, a1.w, h1, l1);
    ohu[64 + lane * 2] = h0; ohu[64 + lane * 2 + 1] = h1;
    olu[64 + lane * 2] = l0; olu[64 + lane * 2 + 1] = l1;
}

// ---------------- bf16 HMMA 3-split GEMM, 2-stage, occ=2, paired via z -----
// N fixed at 256. blockIdx.z selects problem 0/1; CTAs beyond M exit early.
#define A_ST 80
#define B_ST 272
#define OFF_AL 10240
#define OFF_BH 20480
#define OFF_BL 29184
#define STAGE 37888
#define NSTAGE 2

struct GProb {
    const ushortx *ah0, *al0, *ah1, *al1, *ah2, *al2, *Bh, *Bl;
    const float* bias;
    float* C;
    ushortx *Ch, *Cl;
    int M, Ktot, Kseg, relu;
};

__global__ __launch_bounds__(256, 2) void k_bgemm(GProb p0, GProb p1) {
    extern __shared__ char smc[];
    const GProb& P = (blockIdx.z == 0) ? p0 : p1;
    const int bm = blockIdx.y * 128;
    const int M = P.M;
    if (bm >= M) return;  // uniform per-CTA
    const ushortx* ah0 = P.ah0; const ushortx* al0 = P.al0;
    const ushortx* ah1 = P.ah1; const ushortx* al1 = P.al1;
    const ushortx* ah2 = P.ah2; const ushortx* al2 = P.al2;
    const ushortx* Bh = P.Bh;   const ushortx* Bl = P.Bl;
    const int Ktot = P.Ktot, Kseg = P.Kseg, relu = P.relu;
    const int N = 256;

    const int tid = threadIdx.x;
    const int lane = tid & 31;
    const int warp = tid >> 5;
    const int g = lane >> 2;
    const int t = lane & 3;
    const int wm = warp & 1;
    const int wn = warp >> 1;
    const int bn = blockIdx.x * 128;
    const unsigned sbase = smem_u32(smc);
    const int NIT = Ktot >> 5;
    const int segC = Kseg >> 5;

    float acc[4][4][4];
#pragma unroll
    for (int i = 0; i < 4; ++i)
#pragma unroll
        for (int j = 0; j < 4; ++j)
#pragma unroll
            for (int q = 0; q < 4; ++q) acc[i][j][q] = 0.f;

    const int ca = tid * 2;
    const int arow0 = ca >> 2, ac0 = ca & 3;
    const int arow1 = (ca + 1) >> 2, ac1 = (ca + 1) & 3;
    const int brow0 = ca >> 4, bc0 = ca & 15;
    const int brow1 = (ca + 1) >> 4, bc1 = (ca + 1) & 15;

    auto issue = [&](int it) {
        int seg = it / segC;
        int kloc = (it - seg * segC) << 5;
        const ushortx* pah = (seg == 0) ? ah0 : ((seg == 1) ? ah1 : ah2);
        const ushortx* pal = (seg == 0) ? al0 : ((seg == 1) ? al1 : al2);
        unsigned sa = sbase + (it & 1) * STAGE;
        int gr0 = bm + arow0, gr1 = bm + arow1;
        int ok0 = gr0 < M ? 16 : 0, ok1 = gr1 < M ? 16 : 0;
        size_t off0 = (size_t)(gr0 < M ? gr0 : 0) * Kseg + kloc + ac0 * 8;
        size_t off1 = (size_t)(gr1 < M ? gr1 : 0) * Kseg + kloc + ac1 * 8;
        cp16(sa + arow0 * A_ST + ac0 * 16, pah + off0, ok0);
        cp16(sa + arow1 * A_ST + ac1 * 16, pah + off1, ok1);
        cp16(sa + OFF_AL + arow0 * A_ST + ac0 * 16, pal + off0, ok0);
        cp16(sa + OFF_AL + arow1 * A_ST + ac1 * 16, pal + off1, ok1);
        int kg = it << 5;
        size_t bo0 = (size_t)(kg + brow0) * N + bn + bc0 * 8;
        size_t bo1 = (size_t)(kg + brow1) * N + bn + bc1 * 8;
        cp16(sa + OFF_BH + brow0 * B_ST + bc0 * 16, Bh + bo0, 16);
        cp16(sa + OFF_BH + brow1 * B_ST + bc1 * 16, Bh + bo1, 16);
        cp16(sa + OFF_BL + brow0 * B_ST + bc0 * 16, Bl + bo0, 16);
        cp16(sa + OFF_BL + brow1 * B_ST + bc1 * 16, Bl + bo1, 16);
        CP_COMMIT();
    };

    issue(0);
    for (int it = 0; it < NIT; ++it) {
        CP_WAIT0();
        __syncthreads();
        if (it + 1 < NIT) issue(it + 1);
        const unsigned sa = sbase + (it & 1) * STAGE;
#pragma unroll
        for (int kk = 0; kk < 2; ++kk) {
            unsigned ah[4][4], al[4][4], bh[2][4], bl[2][4];
            unsigned abase = sa + (wm * 64 + (lane & 15)) * A_ST + kk * 32 + ((lane >> 4) << 4);
#pragma unroll
            for (int i = 0; i < 4; ++i) {
                LDSM4(ah[i], abase + i * (16 * A_ST));
                LDSM4(al[i], abase + i * (16 * A_ST) + OFF_AL);
            }
            unsigned bbase = sa + OFF_BH + (kk * 16 + (lane & 15)) * B_ST +
                             (wn * 32 + ((lane >> 4) << 3)) * 2;
#pragma unroll
            for (int p = 0; p < 2; ++p) {
                LDSM4T(bh[p], bbase + p * 32);
                LDSM4T(bl[p], bbase + p * 32 + (OFF_BL - OFF_BH));
            }
#pragma unroll
            for (int i = 0; i < 4; ++i)
#pragma unroll
                for (int j = 0; j < 4; ++j) {
                    unsigned* bhj = &bh[j >> 1][(j & 1) * 2];
                    unsigned* blj = &bl[j >> 1][(j & 1) * 2];
                    MMA16816(acc[i][j], ah[i], bhj);
                    MMA16816(acc[i][j], ah[i], blj);
                    MMA16816(acc[i][j], al[i], bhj);
                }
        }
    }

    float* C = P.C;
    ushortx* Ch = P.Ch;
    ushortx* Cl = P.Cl;
    const float* bias = P.bias;
#pragma unroll
    for (int i = 0; i < 4; ++i) {
        int r0 = bm + wm * 64 + i * 16 + g;
#pragma unroll
        for (int j = 0; j < 4; ++j) {
            int cn = bn + wn * 32 + j * 8 + 2 * t;
            float2 bv = make_float2(0.f, 0.f);
            if (bias) bv = *(const float2*)(bias + cn);
#pragma unroll
            for (int h = 0; h < 2; ++h) {
                int row = r0 + h * 8;
                if (row >= M) continue;
                float vx = acc[i][j][h * 2 + 0] + bv.x;
                float vy = acc[i][j][h * 2 + 1] + bv.y;
                if (relu) { vx = fmaxf(vx, 0.f); vy = fmaxf(vy, 0.f); }
                size_t o = (size_t)row * N + cn;
                if (C) *(float2*)(C + o) = make_float2(vx, vy);
                if (Ch) {
                    unsigned hh, ll;
                    bsplit(vx, vy, hh, ll);
                    *(unsigned*)(Ch + o) = hh;
                    *(unsigned*)(Cl + o) = ll;
                }
            }
        }
    }
}

// ---------------- fp32 SGEMM (N=40 head only) ----------------
#define BM 128
#define BN 64
#define BK 16
#define TM 8
#define TN 4
__global__ __launch_bounds__(256) void k_sgemm(
    const float* __restrict__ A, const float* __restrict__ B,
    const float* __restrict__ bias, float* __restrict__ C,
    int M, int N, int K) {
    __shared__ float As[BK][BM];
    __shared__ float Bs[BK][BN];
    const int tid = threadIdx.x;
    const int tx = tid & 15, ty = tid >> 4;
    const int bm = blockIdx.y * BM, bn = blockIdx.x * BN;
    float acc[TM][TN];
#pragma unroll
    for (int i = 0; i < TM; ++i)
#pragma unroll
        for (int j = 0; j < TN; ++j) acc[i][j] = 0.f;
    const int ar = tid >> 2, ac = (tid & 3) << 2;
    const int br = tid >> 4, bc = (tid & 15) << 2;
    for (int k0 = 0; k0 < K; k0 += BK) {
#pragma unroll
        for (int h = 0; h < 2; ++h) {
            int r = ar + h * 64, gr = bm + r;
            float4 v = make_float4(0.f, 0.f, 0.f, 0.f);
            if (gr < M) v = *(const float4*)(A + (size_t)gr * K + k0 + ac);
            As[ac + 0][r] = v.x; As[ac + 1][r] = v.y;
            As[ac + 2][r] = v.z; As[ac + 3][r] = v.w;
        }
        {
            int gc = bn + bc;
            float4 v = make_float4(0.f, 0.f, 0.f, 0.f);
            if (gc < N) v = *(const float4*)(B + (size_t)(k0 + br) * N + gc);
            *(float4*)&Bs[br][bc] = v;
        }
        __syncthreads();
#pragma unroll
        for (int kk = 0; kk < BK; ++kk) {
            float aF[TM], bF[TN];
#pragma unroll
            for (int i = 0; i < TM; ++i) aF[i] = As[kk][ty * TM + i];
#pragma unroll
            for (int j = 0; j < TN; ++j) bF[j] = Bs[kk][tx * TN + j];
#pragma unroll
            for (int i = 0; i < TM; ++i)
#pragma unroll
                for (int j = 0; j < TN; ++j) acc[i][j] = fmaf(aF[i], bF[j], acc[i][j]);
        }
        __syncthreads();
    }
    const int col = bn + tx * TN;
    if (col < N) {
        float4 bv = make_float4(0.f, 0.f, 0.f, 0.f);
        if (bias) bv = *(const float4*)(bias + col);
#pragma unroll
        for (int i = 0; i < TM; ++i) {
            int row = bm + ty * TM + i;
            if (row >= M) continue;
            *(float4*)(C + (size_t)row * N + col) =
                make_float4(acc[i][0] + bv.x, acc[i][1] + bv.y,
                            acc[i][2] + bv.z, acc[i][3] + bv.w);
        }
    }
}

// ---------------- fused relu+residual+LayerNorm + split, both node types ---
__global__ void k_ln2(const float* __restrict__ ta, float* __restrict__ ha,
                      ushortx* __restrict__ hah, ushortx* __restrict__ hal,
                      const float* __restrict__ ga_, const float* __restrict__ ba_,
                      const float* __restrict__ tp, float* __restrict__ hp,
                      ushortx* __restrict__ hph, ushortx* __restrict__ hpl,
                      const float* __restrict__ gp_, const float* __restrict__ bp_) {
    int w = (blockIdx.x * blockDim.x + threadIdx.x) >> 5;
    int lane = threadIdx.x & 31;
    const float* t;
    float* h;
    ushortx *hh, *hl;
    const float *g, *b;
    if (w < AN) {
        t = ta; h = ha; hh = hah; hl = hal; g = ga_; b = ba_;
    } else if (w < AN + PN) {
        w -= AN;
        t = tp; h = hp; hh = hph; hl = hpl; g = gp_; b = bp_;
    } else return;
    const float4* t4 = (const float4*)(t + (size_t)w * HD);
    float4* h4 = (float4*)(h + (size_t)w * HD);
    float4 x0 = t4[lane], x1 = t4[lane + 32];
    float4 p0 = h4[lane], p1 = h4[lane + 32];
    float u[8];
    u[0] = fmaxf(x0.x, 0.f) + p0.x; u[1] = fmaxf(x0.y, 0.f) + p0.y;
    u[2] = fmaxf(x0.z, 0.f) + p0.z; u[3] = fmaxf(x0.w, 0.f) + p0.w;
    u[4] = fmaxf(x1.x, 0.f) + p1.x; u[5] = fmaxf(x1.y, 0.f) + p1.y;
    u[6] = fmaxf(x1.z, 0.f) + p1.z; u[7] = fmaxf(x1.w, 0.f) + p1.w;
    float s = 0.f;
#pragma unroll
    for (int i = 0; i < 8; ++i) s += u[i];
    s = warp_sum(s);
    float mu = s * (1.f / HD);
    float v = 0.f;
#pragma unroll
    for (int i = 0; i < 8; ++i) { float d = u[i] - mu; v += d * d; }
    v = warp_sum(v);
    float rstd = rsqrtf(v * (1.f / HD) + 1e-5f);
    const float4* g4 = (const float4*)g;
    const float4* b4 = (const float4*)b;
    float4 ga = g4[lane], gb = g4[lane + 32];
    float4 ba = b4[lane], bb = b4[lane + 32];
    float o[8];
    o[0] = (u[0] - mu) * rstd * ga.x + ba.x; o[1] = (u[1] - mu) * rstd * ga.y + ba.y;
    o[2] = (u[2] - mu) * rstd * ga.z + ba.z; o[3] = (u[3] - mu) * rstd * ga.w + ba.w;
    o[4] = (u[4] - mu) * rstd * gb.x + bb.x; o[5] = (u[5] - mu) * rstd * gb.y + bb.y;
    o[6] = (u[6] - mu) * rstd * gb.z + bb.z; o[7] = (u[7] - mu) * rstd * gb.w + bb.w;
    h4[lane] = make_float4(o[0], o[1], o[2], o[3]);
    h4[lane + 32] = make_float4(o[4], o[5], o[6], o[7]);
    unsigned* hhu = (unsigned*)(hh + (size_t)w * HD);
    unsigned* hlu = (unsigned*)(hl + (size_t)w * HD);
    unsigned hv0, lv0, hv1, lv1;
    bsplit(o[0], o[1], hv0, lv0); bsplit(o[2], o[3], hv1, lv1);
    hhu[lane * 2] = hv0; hhu[lane * 2 + 1] = hv1;
    hlu[lane * 2] = lv0; hlu[lane * 2 + 1] = lv1;
    bsplit(o[4], o[5], hv0, lv0); bsplit(o[6], o[7], hv1, lv1);
    hhu[64 + lane * 2] = hv0; hhu[64 + lane * 2 + 1] = hv1;
    hlu[64 + lane * 2] = lv0; hlu[64 + lane * 2 + 1] = lv1;
}

__global__ void k_lsm(float* __restrict__ x, int rows) {
    int w = (blockIdx.x * blockDim.x + threadIdx.x) >> 5;
    int lane = threadIdx.x & 31;
    if (w >= rows) return;
    float* r = x + (size_t)w * CN;
    float v0 = r[lane];
    bool has1 = (lane + 32) < CN;
    float v1 = has1 ? r[lane + 32] : -3.4e38f;
    float m = warp_max(fmaxf(v0, v1));
    float s = expf(v0 - m) + (has1 ? expf(v1 - m) : 0.f);
    s = warp_sum(s);
    float lse = m + logf(s);
    r[lane] = v0 - lse;
    if (has1) r[lane + 32] = v1 - lse;
}

// ---------------- host ----------------
static GProb mkprob(const ushortx* ah0, const ushortx* al0,
                    const ushortx* ah1, const ushortx* al1,
                    const ushortx* ah2, const ushortx* al2,
                    const ushortx* Bh, const ushortx* Bl,
                    const float* bias, float* C, ushortx* Ch, ushortx* Cl,
                    int M, int Ktot, int Kseg, int relu) {
    GProb p;
    p.ah0 = ah0; p.al0 = al0; p.ah1 = ah1; p.al1 = al1; p.ah2 = ah2; p.al2 = al2;
    p.Bh = Bh; p.Bl = Bl; p.bias = bias; p.C = C; p.Ch = Ch; p.Cl = Cl;
    p.M = M; p.Ktot = Ktot; p.Kseg = Kseg; p.relu = relu;
    return p;
}
static inline void bgemm2(const GProb& p0, const GProb& p1, int nz) {
    int my = (p0.M + 127) >> 7;
    if (nz == 2) { int m1 = (p1.M + 127) >> 7; if (m1 > my) my = m1; }
    dim3 grid(2, my, nz);
    k_bgemm<<<grid, 256, NSTAGE * STAGE>>>(p0, p1);
}

extern "C" void kernel_launch(void* const* d_in, const int* in_sizes, int n_in,
                              void* d_out, int out_size) {
    const float* x_author     = (const float*)d_in[0];
    const float* x_paper      = (const float*)d_in[1];
    const int*   e0_src       = (const int*)d_in[2];
    const int*   e0_dst       = (const int*)d_in[3];
    const int*   e1_src       = (const int*)d_in[4];
    const int*   e1_dst       = (const int*)d_in[5];
    const int*   e2_src       = (const int*)d_in[6];
    const int*   e2_dst       = (const int*)d_in[7];
    const float* emb_W_author = (const float*)d_in[8];
    const float* emb_b_author = (const float*)d_in[9];
    const float* emb_W_paper  = (const float*)d_in[10];
    const float* emb_b_paper  = (const float*)d_in[11];
    const float* W_self       = (const float*)d_in[12];
    const float* W_neigh      = (const float*)d_in[13];
    const float* b_conv       = (const float*)d_in[14];
    const float* ln_g_author  = (const float*)d_in[15];
    const float* ln_b_author  = (const float*)d_in[16];
    const float* ln_g_paper   = (const float*)d_in[17];
    const float* ln_b_paper   = (const float*)d_in[18];
    const float* pW1_author   = (const float*)d_in[19];
    const float* pb1_author   = (const float*)d_in[20];
    const float* pW2_author   = (const float*)d_in[21];
    const float* pb2_author   = (const float*)d_in[22];
    const float* pW1_paper    = (const float*)d_in[23];
    const float* pb1_paper    = (const float*)d_in[24];
    const float* pW2_paper    = (const float*)d_in[25];
    const float* pb2_paper    = (const float*)d_in[26];

    cudaFuncSetAttribute(k_bgemm, cudaFuncAttributeMaxDynamicSharedMemorySize, NSTAGE * STAGE);

    float *p_ha, *p_hp, *p_ta, *p_tp, *p_b01;
    ushortx *p_xah, *p_xal, *p_xph, *p_xpl, *p_hah, *p_hal, *p_hph, *p_hpl;
    ushortx *p_ag0h, *p_ag0l, *p_ag1h, *p_ag1l, *p_ag2h, *p_ag2l, *p_wh, *p_wl;
    int *p_deg, *p_off, *p_cur, *p_perm, *p_part;
    cudaGetSymbolAddress((void**)&p_ha, g_ha);
    cudaGetSymbolAddress((void**)&p_hp, g_hp);
    cudaGetSymbolAddress((void**)&p_ta, g_ta);
    cudaGetSymbolAddress((void**)&p_tp, g_tp);
    cudaGetSymbolAddress((void**)&p_b01, g_b01);
    cudaGetSymbolAddress((void**)&p_xah, g_xah);
    cudaGetSymbolAddress((void**)&p_xal, g_xal);
    cudaGetSymbolAddress((void**)&p_xph, g_xph);
    cudaGetSymbolAddress((void**)&p_xpl, g_xpl);
    cudaGetSymbolAddress((void**)&p_hah, g_hah);
    cudaGetSymbolAddress((void**)&p_hal, g_hal);
    cudaGetSymbolAddress((void**)&p_hph, g_hph);
    cudaGetSymbolAddress((void**)&p_hpl, g_hpl);
    cudaGetSymbolAddress((void**)&p_ag0h, g_ag0h);
    cudaGetSymbolAddress((void**)&p_ag0l, g_ag0l);
    cudaGetSymbolAddress((void**)&p_ag1h, g_ag1h);
    cudaGetSymbolAddress((void**)&p_ag1l, g_ag1l);
    cudaGetSymbolAddress((void**)&p_ag2h, g_ag2h);
    cudaGetSymbolAddress((void**)&p_ag2l, g_ag2l);
    cudaGetSymbolAddress((void**)&p_wh, g_wh);
    cudaGetSymbolAddress((void**)&p_wl, g_wl);
    cudaGetSymbolAddress((void**)&p_deg, g_deg);
    cudaGetSymbolAddress((void**)&p_off, g_off);
    cudaGetSymbolAddress((void**)&p_cur, g_cur);
    cudaGetSymbolAddress((void**)&p_perm, g_perm);
    cudaGetSymbolAddress((void**)&p_part, g_part);

    // ---- all input/weight/bias splits in ONE launch ----
    k_split_all<<<(NSPLIT_TOT + 255) / 256, 256>>>(
        x_author, x_paper, emb_W_author, emb_W_paper, W_self, W_neigh,
        pW1_author, pW1_paper, pW2_paper, b_conv,
        p_wh, p_wl, p_xah, p_xal, p_xph, p_xpl, p_b01);

    // ---- CSR build ----
    k_zero3<<<(3 * PN + 255) / 256, 256>>>(p_deg);
    k_hist3<<<(3 * EN + 255) / 256, 256>>>(e0_dst, e1_dst, e2_dst, p_deg);
    k_scan_sum<<<NBT, 1024>>>(p_deg, p_part);
    k_scan_top<<<1, 32>>>(p_part, p_off);
    k_scan_apply<<<NBT, 1024>>>(p_deg, p_part, p_off, p_cur);
    k_fill3<<<(3 * EN + 255) / 256, 256>>>(e0_src, e0_dst, e1_src, e1_dst,
                                           e2_src, e2_dst, p_cur, p_perm);

    // ---- embeddings: BOTH in one launch ----
    bgemm2(mkprob(p_xah, p_xal, 0, 0, 0, 0, p_wh + WOFF_EMBA, p_wl + WOFF_EMBA,
                  emb_b_author, p_ha, p_hah, p_hal, AN, DIN, DIN, 0),
           mkprob(p_xph, p_xpl, 0, 0, 0, 0, p_wh + WOFF_EMBP, p_wl + WOFF_EMBP,
                  emb_b_paper, p_hp, p_hph, p_hpl, PN, DIN, DIN, 0), 2);

    // ---- 2 SAGE layers (3 launches per layer) ----
    const int WPO[2] = {WOFF_WP0, WOFF_WP1};
    const int WAO[2] = {WOFF_WA0, WOFF_WA1};
    const int NWARP_AGG = 2 * PN + AN;
    for (int l = 0; l < 2; ++l) {
        const float* bc = b_conv + (size_t)l * 3 * HD;
        k_agg3<<<(NWARP_AGG * 32 + 127) / 128, 128>>>(
            p_ha, p_hp, p_off, p_perm,
            p_ag0h, p_ag0l, p_ag1h, p_ag1l, p_ag2h, p_ag2l);
        bgemm2(mkprob(p_hph, p_hpl, p_ag0h, p_ag0l, p_ag1h, p_ag1l,
                      p_wh + WPO[l], p_wl + WPO[l], p_b01 + l * HD,
                      p_tp, 0, 0, PN, 3 * HD, HD, 0),
               mkprob(p_hah, p_hal, p_ag2h, p_ag2l, 0, 0,
                      p_wh + WAO[l], p_wl + WAO[l], bc + 2 * HD,
                      p_ta, 0, 0, AN, 2 * HD, HD, 0), 2);
        k_ln2<<<((AN + PN) * 32 + 127) / 128, 128>>>(
            p_ta, p_ha, p_hah, p_hal, ln_g_author, ln_b_author,
            p_tp, p_hp, p_hph, p_hpl, ln_g_paper, ln_b_paper);
    }

    // ---- output heads: both P1 GEMMs in one launch ----
    float* out = (float*)d_out;
    bgemm2(mkprob(p_hah, p_hal, 0, 0, 0, 0, p_wh + WOFF_P1A, p_wl + WOFF_P1A,
                  pb1_author, p_ta, 0, 0, AN, HD, HD, 1),
           mkprob(p_hph, p_hpl, 0, 0, 0, 0, p_wh + WOFF_P1P, p_wl + WOFF_P1P,
                  pb1_paper, 0, p_ag0h, p_ag0l, PN, HD, HD, 1), 2);
    // paper P2 (bf16) and author N=40 head (fp32) + log_softmax
    bgemm2(mkprob(p_ag0h, p_ag0l, 0, 0, 0, 0, p_wh + WOFF_P2P, p_wl + WOFF_P2P,
                  pb2_paper, out + (size_t)AN * CN, 0, 0, PN, HD, HD, 0),
           mkprob(0, 0, 0, 0, 0, 0, 0, 0, 0, 0, 0, 0, 0, HD, HD, 0), 1);
    {
        dim3 grid((CN + BN - 1) / BN, (AN + BM - 1) / BM);
        k_sgemm<<<grid, 256>>>(p_ta, pW2_author, pb2_author, out, AN, CN, HD);
    }
    k_lsm<<<(AN * 32 + 127) / 128, 128>>>(out, AN);
}

// round 14
// speedup vs baseline: 1.0786x; 1.0406x over previous
#include <cuda_runtime.h>
#include <cuda_bf16.h>
#include <math.h>

#define AN 50000
#define PN 100000
#define DIN 128
#define HD 256
#define CN 40
#define EN 300000

typedef unsigned short ushortx;

// fp32 conv outputs only (pre-LN); hidden state lives as bf16 hi/lo pairs
__device__ float g_ta[(size_t)AN * HD];
__device__ float g_tp[(size_t)PN * HD];
__device__ float g_b01[2 * HD];
__device__ ushortx g_xah[(size_t)AN * DIN], g_xal[(size_t)AN * DIN];
__device__ ushortx g_xph[(size_t)PN * DIN], g_xpl[(size_t)PN * DIN];
__device__ ushortx g_hah[(size_t)AN * HD],  g_hal[(size_t)AN * HD];
__device__ ushortx g_hph[(size_t)PN * HD],  g_hpl[(size_t)PN * HD];
__device__ ushortx g_ag0h[(size_t)PN * HD], g_ag0l[(size_t)PN * HD];
__device__ ushortx g_ag1h[(size_t)PN * HD], g_ag1l[(size_t)PN * HD];
__device__ ushortx g_ag2h[(size_t)AN * HD], g_ag2l[(size_t)AN * HD];
// split weights, stacked segments
#define WOFF_EMBA 0
#define WOFF_EMBP (WOFF_EMBA + 128 * 256)
#define WOFF_WP0  (WOFF_EMBP + 128 * 256)
#define WOFF_WA0  (WOFF_WP0 + 768 * 256)
#define WOFF_WP1  (WOFF_WA0 + 512 * 256)
#define WOFF_WA1  (WOFF_WP1 + 768 * 256)
#define WOFF_P1A  (WOFF_WA1 + 512 * 256)
#define WOFF_P1P  (WOFF_P1A + 256 * 256)
#define WOFF_P2P  (WOFF_P1P + 256 * 256)
#define WTOT      (WOFF_P2P + 256 * 256)
__device__ ushortx g_wh[WTOT], g_wl[WTOT];
// CSR
#define NB_P 98
#define NB_A 49
#define NBT (NB_P + NB_P + NB_A)
__device__ int g_deg[3 * PN];
__device__ int g_off[3 * (PN + 1)];
__device__ int g_cur[3 * PN];
__device__ int g_perm[3 * EN];
__device__ int g_part[NBT];

// ---------------- helpers ----------------
__device__ __forceinline__ unsigned smem_u32(const void* p) {
    unsigned a;
    asm("{ .reg .u64 t; cvta.to.shared.u64 t, %1; cvt.u32.u64 %0, t; }" : "=r"(a) : "l"(p));
    return a;
}
__device__ __forceinline__ void cp16(unsigned dst, const void* src, int n) {
    asm volatile("cp.async.cg.shared.global [%0], [%1], 16, %2;" :: "r"(dst), "l"(src), "r"(n));
}
#define CP_COMMIT() asm volatile("cp.async.commit_group;" ::: "memory")
#define CP_WAIT0()  asm volatile("cp.async.wait_group 0;" ::: "memory")

__device__ __forceinline__ void bsplit(float x, float y, unsigned& h, unsigned& l) {
    __nv_bfloat162 hb = __floats2bfloat162_rn(x, y);
    float rx = x - __bfloat162float(hb.x);
    float ry = y - __bfloat162float(hb.y);
    __nv_bfloat162 lb = __floats2bfloat162_rn(rx, ry);
    h = *(unsigned*)&hb;
    l = *(unsigned*)&lb;
}
__device__ __forceinline__ float2 b2f2(unsigned u) {
    __nv_bfloat162 t = *(__nv_bfloat162*)&u;
    return make_float2(__bfloat162float(t.x), __bfloat162float(t.y));
}
#define MMA16816(c, a, b) \
    asm volatile("mma.sync.aligned.m16n8k16.row.col.f32.bf16.bf16.f32 " \
        "{%0,%1,%2,%3},{%4,%5,%6,%7},{%8,%9},{%0,%1,%2,%3};" \
        : "+f"((c)[0]), "+f"((c)[1]), "+f"((c)[2]), "+f"((c)[3]) \
        : "r"((a)[0]), "r"((a)[1]), "r"((a)[2]), "r"((a)[3]), "r"((b)[0]), "r"((b)[1]))
#define LDSM4(r, addr) \
    asm volatile("ldmatrix.sync.aligned.m8n8.x4.shared.b16 {%0,%1,%2,%3},[%4];" \
        : "=r"((r)[0]), "=r"((r)[1]), "=r"((r)[2]), "=r"((r)[3]) : "r"(addr))
#define LDSM4T(r, addr) \
    asm volatile("ldmatrix.sync.aligned.m8n8.x4.trans.shared.b16 {%0,%1,%2,%3},[%4];" \
        : "=r"((r)[0]), "=r"((r)[1]), "=r"((r)[2]), "=r"((r)[3]) : "r"(addr))

__device__ __forceinline__ float warp_sum(float v) {
#pragma unroll
    for (int o = 16; o; o >>= 1) v += __shfl_xor_sync(0xffffffffu, v, o);
    return v;
}
__device__ __forceinline__ int warp_sumi(int v) {
#pragma unroll
    for (int o = 16; o; o >>= 1) v += __shfl_xor_sync(0xffffffffu, v, o);
    return v;
}

// ---------------- mega split kernel (+ deg zeroing) ----------------
#define NXA (AN * DIN)
#define NXP (PN * DIN)
#define NSPLIT_TOT (NXA + NXP + WTOT + 512 + 3 * PN)

__global__ void k_split_all(
    const float* __restrict__ x_author, const float* __restrict__ x_paper,
    const float* __restrict__ emb_W_author, const float* __restrict__ emb_W_paper,
    const float* __restrict__ W_self, const float* __restrict__ W_neigh,
    const float* __restrict__ pW1_author, const float* __restrict__ pW1_paper,
    const float* __restrict__ pW2_paper, const float* __restrict__ b_conv,
    ushortx* __restrict__ wh, ushortx* __restrict__ wl,
    ushortx* __restrict__ xah, ushortx* __restrict__ xal,
    ushortx* __restrict__ xph, ushortx* __restrict__ xpl,
    float* __restrict__ b01, int* __restrict__ deg) {
    int i = blockIdx.x * blockDim.x + threadIdx.x;
    if (i >= NSPLIT_TOT) return;
    if (i < NXA) {
        float v = x_author[i];
        __nv_bfloat16 h = __float2bfloat16(v);
        xah[i] = *(ushortx*)&h;
        __nv_bfloat16 l = __float2bfloat16(v - __bfloat162float(h));
        xal[i] = *(ushortx*)&l;
        return;
    }
    i -= NXA;
    if (i < NXP) {
        float v = x_paper[i];
        __nv_bfloat16 h = __float2bfloat16(v);
        xph[i] = *(ushortx*)&h;
        __nv_bfloat16 l = __float2bfloat16(v - __bfloat162float(h));
        xpl[i] = *(ushortx*)&l;
        return;
    }
    i -= NXP;
    if (i < WTOT) {
        const int j = i;
        const int Q = 65536;
        float v;
        if (j < Q)               v = (j < Q / 2) ? emb_W_author[j] : emb_W_paper[j - Q / 2];
        else if (j < 2 * Q)      { int r = j - Q;     v = W_self[r] + W_self[Q + r]; }
        else if (j < 3 * Q)      v = W_neigh[j - 2 * Q];
        else if (j < 4 * Q)      v = W_neigh[Q + j - 3 * Q];
        else if (j < 5 * Q)      v = W_self[2 * Q + j - 4 * Q];
        else if (j < 6 * Q)      v = W_neigh[2 * Q + j - 5 * Q];
        else if (j < 7 * Q)      { int r = j - 6 * Q; v = W_self[3 * Q + r] + W_self[4 * Q + r]; }
        else if (j < 8 * Q)      v = W_neigh[3 * Q + j - 7 * Q];
        else if (j < 9 * Q)      v = W_neigh[4 * Q + j - 8 * Q];
        else if (j < 10 * Q)     v = W_self[5 * Q + j - 9 * Q];
        else if (j < 11 * Q)     v = W_neigh[5 * Q + j - 10 * Q];
        else if (j < 12 * Q)     v = pW1_author[j - 11 * Q];
        else if (j < 13 * Q)     v = pW1_paper[j - 12 * Q];
        else                     v = pW2_paper[j - 13 * Q];
        __nv_bfloat16 h = __float2bfloat16(v);
        wh[j] = *(ushortx*)&h;
        __nv_bfloat16 l = __float2bfloat16(v - __bfloat162float(h));
        wl[j] = *(ushortx*)&l;
        return;
    }
    i -= WTOT;
    if (i < 512) {
        int l = i >> 8, c = i & 255;
        b01[i] = b_conv[l * 768 + c] + b_conv[l * 768 + 256 + c];
        return;
    }
    i -= 512;
    deg[i] = 0;
}

// ---------------- CSR build ----------------
__global__ void k_hist3(const int* __restrict__ d0, const int* __restrict__ d1,
                        const int* __restrict__ d2, int* __restrict__ deg) {
    int i = blockIdx.x * blockDim.x + threadIdx.x;
    if (i >= 3 * EN) return;
    int t = i / EN, k = i - t * EN;
    const int* d = (t == 0) ? d0 : ((t == 1) ? d1 : d2);
    atomicAdd(&deg[t * PN + d[k]], 1);
}
__device__ __forceinline__ void scan_block_coords(int b, int& t, int& blk, int& nd) {
    if (b < NB_P)            { t = 0; blk = b;              nd = PN; }
    else if (b < 2 * NB_P)   { t = 1; blk = b - NB_P;       nd = PN; }
    else                     { t = 2; blk = b - 2 * NB_P;   nd = AN; }
}
__global__ void k_scan_sum(const int* __restrict__ deg, int* __restrict__ part) {
    __shared__ int sh[32];
    int t, blk, nd;
    scan_block_coords(blockIdx.x, t, blk, nd);
    int i = blk * 1024 + threadIdx.x;
    int v = (i < nd) ? deg[t * PN + i] : 0;
    v = warp_sumi(v);
    if ((threadIdx.x & 31) == 0) sh[threadIdx.x >> 5] = v;
    __syncthreads();
    if (threadIdx.x < 32) {
        int x = sh[threadIdx.x];
        x = warp_sumi(x);
        if (threadIdx.x == 0) part[blockIdx.x] = x;
    }
}
__global__ void k_scan_top(int* __restrict__ part, int* __restrict__ off) {
    int t = threadIdx.x;
    if (t >= 3) return;
    int base = (t == 0) ? 0 : ((t == 1) ? NB_P : 2 * NB_P);
    int n = (t == 2) ? NB_A : NB_P;
    int nd = (t == 2) ? AN : PN;
    int run = 0;
    for (int i = 0; i < n; ++i) { int v = part[base + i]; part[base + i] = run; run += v; }
    off[t * (PN + 1) + nd] = run;
}
__global__ void k_scan_apply(const int* __restrict__ deg, const int* __restrict__ part,
                             int* __restrict__ off, int* __restrict__ cur) {
    __shared__ int sh[1024];
    int t, blk, nd;
    scan_block_coords(blockIdx.x, t, blk, nd);
    int i = blk * 1024 + threadIdx.x;
    int v = (i < nd) ? deg[t * PN + i] : 0;
    sh[threadIdx.x] = v;
    __syncthreads();
#pragma unroll
    for (int d = 1; d < 1024; d <<= 1) {
        int x = (threadIdx.x >= d) ? sh[threadIdx.x - d] : 0;
        __syncthreads();
        sh[threadIdx.x] += x;
        __syncthreads();
    }
    if (i < nd) {
        int o = part[blockIdx.x] + sh[threadIdx.x] - v;
        off[t * (PN + 1) + i] = o;
        cur[t * PN + i] = o;
    }
}
__global__ void k_fill3(const int* __restrict__ s0, const int* __restrict__ d0,
                        const int* __restrict__ s1, const int* __restrict__ d1,
                        const int* __restrict__ s2, const int* __restrict__ d2,
                        int* __restrict__ cur, int* __restrict__ perm) {
    int i = blockIdx.x * blockDim.x + threadIdx.x;
    if (i >= 3 * EN) return;
    int t = i / EN, k = i - t * EN;
    const int* s = (t == 0) ? s0 : ((t == 1) ? s1 : s2);
    const int* d = (t == 0) ? d0 : ((t == 1) ? d1 : d2);
    int slot = atomicAdd(&cur[t * PN + d[k]], 1);
    perm[t * EN + slot] = s[k];
}

// ---------------- 3 mean aggregations, gather from bf16 hi/lo state --------
__global__ void k_agg3(const ushortx* __restrict__ hah, const ushortx* __restrict__ hal,
                       const ushortx* __restrict__ hph, const ushortx* __restrict__ hpl,
                       const int* __restrict__ off, const int* __restrict__ perm,
                       ushortx* __restrict__ ag0h, ushortx* __restrict__ ag0l,
                       ushortx* __restrict__ ag1h, ushortx* __restrict__ ag1l,
                       ushortx* __restrict__ ag2h, ushortx* __restrict__ ag2l) {
    int w = (blockIdx.x * blockDim.x + threadIdx.x) >> 5;
    int lane = threadIdx.x & 31;
    const ushortx *sh_, *sl_;
    const int* of;
    const int* pm;
    ushortx *oh, *ol;
    if (w < PN) {
        sh_ = hah; sl_ = hal; of = off; pm = perm; oh = ag0h; ol = ag0l;
    } else if (w < 2 * PN) {
        w -= PN;
        sh_ = hph; sl_ = hpl; of = off + (PN + 1); pm = perm + EN; oh = ag1h; ol = ag1l;
    } else if (w < 2 * PN + AN) {
        w -= 2 * PN;
        sh_ = hph; sl_ = hpl; of = off + 2 * (PN + 1); pm = perm + 2 * EN; oh = ag2h; ol = ag2l;
    } else return;
    int s = of[w], e = of[w + 1];
    float a[8];
#pragma unroll
    for (int q = 0; q < 8; ++q) a[q] = 0.f;
    for (int i = s; i < e; ++i) {
        size_t row = (size_t)pm[i] * HD;
        const uint2* rh = (const uint2*)(sh_ + row);
        const uint2* rl = (const uint2*)(sl_ + row);
        uint2 h0 = __ldg(&rh[lane]), h1 = __ldg(&rh[lane + 32]);
        uint2 l0 = __ldg(&rl[lane]), l1 = __ldg(&rl[lane + 32]);
        float2 f;
        f = b2f2(h0.x); a[0] += f.x; a[1] += f.y;
        f = b2f2(h0.y); a[2] += f.x; a[3] += f.y;
        f = b2f2(h1.x); a[4] += f.x; a[5] += f.y;
        f = b2f2(h1.y); a[6] += f.x; a[7] += f.y;
        f = b2f2(l0.x); a[0] += f.x; a[1] += f.y;
        f = b2f2(l0.y); a[2] += f.x; a[3] += f.y;
        f = b2f2(l1.x); a[4] += f.x; a[5] += f.y;
        f = b2f2(l1.y); a[6] += f.x; a[7] += f.y;
    }
    float inv = (e > s) ? 1.f / (float)(e - s) : 0.f;
#pragma unroll
    for (int q = 0; q < 8; ++q) a[q] *= inv;
    unsigned h0, l0, h1, l1;
    unsigned* ohu = (unsigned*)(oh + (size_t)w * HD);
    unsigned* olu = (unsigned*)(ol + (size_t)w * HD);
    bsplit(a[0], a[1], h0, l0); bsplit(a[2], a[3], h1, l1);
    ohu[lane * 2] = h0; ohu[lane * 2 + 1] = h1;
    olu[lane * 2] = l0; olu[lane * 2 + 1] = l1;
    bsplit(a[4], a[5], h0, l0); bsplit(a[6], a[7], h1, l1);
    ohu[64 + lane * 2] = h0; ohu[64 + lane * 2 + 1] = h1;
    olu[64 + lane * 2] = l0; olu[64 + lane * 2 + 1] = l1;
}

// ---------------- bf16 HMMA 3-split GEMM, 2-stage, occ=2, paired via z -----
#define A_ST 80
#define B_ST 272
#define OFF_AL 10240
#define OFF_BH 20480
#define OFF_BL 29184
#define STAGE 37888
#define NSTAGE 2

struct GProb {
    const ushortx *ah0, *al0, *ah1, *al1, *ah2, *al2, *Bh, *Bl;
    const float* bias;
    float* C;
    ushortx *Ch, *Cl;
    int M, Ktot, Kseg, relu;
};

__global__ __launch_bounds__(256, 2) void k_bgemm(GProb p0, GProb p1) {
    extern __shared__ char smc[];
    const GProb& P = (blockIdx.z == 0) ? p0 : p1;
    const int bm = blockIdx.y * 128;
    const int M = P.M;
    if (bm >= M) return;
    const ushortx* ah0 = P.ah0; const ushortx* al0 = P.al0;
    const ushortx* ah1 = P.ah1; const ushortx* al1 = P.al1;
    const ushortx* ah2 = P.ah2; const ushortx* al2 = P.al2;
    const ushortx* Bh = P.Bh;   const ushortx* Bl = P.Bl;
    const int Ktot = P.Ktot, Kseg = P.Kseg, relu = P.relu;
    const int N = 256;

    const int tid = threadIdx.x;
    const int lane = tid & 31;
    const int warp = tid >> 5;
    const int g = lane >> 2;
    const int t = lane & 3;
    const int wm = warp & 1;
    const int wn = warp >> 1;
    const int bn = blockIdx.x * 128;
    const unsigned sbase = smem_u32(smc);
    const int NIT = Ktot >> 5;
    const int segC = Kseg >> 5;

    float acc[4][4][4];
#pragma unroll
    for (int i = 0; i < 4; ++i)
#pragma unroll
        for (int j = 0; j < 4; ++j)
#pragma unroll
            for (int q = 0; q < 4; ++q) acc[i][j][q] = 0.f;

    const int ca = tid * 2;
    const int arow0 = ca >> 2, ac0 = ca & 3;
    const int arow1 = (ca + 1) >> 2, ac1 = (ca + 1) & 3;
    const int brow0 = ca >> 4, bc0 = ca & 15;
    const int brow1 = (ca + 1) >> 4, bc1 = (ca + 1) & 15;

    auto issue = [&](int it) {
        int seg = it / segC;
        int kloc = (it - seg * segC) << 5;
        const ushortx* pah = (seg == 0) ? ah0 : ((seg == 1) ? ah1 : ah2);
        const ushortx* pal = (seg == 0) ? al0 : ((seg == 1) ? al1 : al2);
        unsigned sa = sbase + (it & 1) * STAGE;
        int gr0 = bm + arow0, gr1 = bm + arow1;
        int ok0 = gr0 < M ? 16 : 0, ok1 = gr1 < M ? 16 : 0;
        size_t off0 = (size_t)(gr0 < M ? gr0 : 0) * Kseg + kloc + ac0 * 8;
        size_t off1 = (size_t)(gr1 < M ? gr1 : 0) * Kseg + kloc + ac1 * 8;
        cp16(sa + arow0 * A_ST + ac0 * 16, pah + off0, ok0);
        cp16(sa + arow1 * A_ST + ac1 * 16, pah + off1, ok1);
        cp16(sa + OFF_AL + arow0 * A_ST + ac0 * 16, pal + off0, ok0);
        cp16(sa + OFF_AL + arow1 * A_ST + ac1 * 16, pal + off1, ok1);
        int kg = it << 5;
        size_t bo0 = (size_t)(kg + brow0) * N + bn + bc0 * 8;
        size_t bo1 = (size_t)(kg + brow1) * N + bn + bc1 * 8;
        cp16(sa + OFF_BH + brow0 * B_ST + bc0 * 16, Bh + bo0, 16);
        cp16(sa + OFF_BH + brow1 * B_ST + bc1 * 16, Bh + bo1, 16);
        cp16(sa + OFF_BL + brow0 * B_ST + bc0 * 16, Bl + bo0, 16);
        cp16(sa + OFF_BL + brow1 * B_ST + bc1 * 16, Bl + bo1, 16);
        CP_COMMIT();
    };

    issue(0);
    for (int it = 0; it < NIT; ++it) {
        CP_WAIT0();
        __syncthreads();
        if (it + 1 < NIT) issue(it + 1);
        const unsigned sa = sbase + (it & 1) * STAGE;
#pragma unroll
        for (int kk = 0; kk < 2; ++kk) {
            unsigned ah[4][4], al[4][4], bh[2][4], bl[2][4];
            unsigned abase = sa + (wm * 64 + (lane & 15)) * A_ST + kk * 32 + ((lane >> 4) << 4);
#pragma unroll
            for (int i = 0; i < 4; ++i) {
                LDSM4(ah[i], abase + i * (16 * A_ST));
                LDSM4(al[i], abase + i * (16 * A_ST) + OFF_AL);
            }
            unsigned bbase = sa + OFF_BH + (kk * 16 + (lane & 15)) * B_ST +
                             (wn * 32 + ((lane >> 4) << 3)) * 2;
#pragma unroll
            for (int p = 0; p < 2; ++p) {
                LDSM4T(bh[p], bbase + p * 32);
                LDSM4T(bl[p], bbase + p * 32 + (OFF_BL - OFF_BH));
            }
#pragma unroll
            for (int i = 0; i < 4; ++i)
#pragma unroll
                for (int j = 0; j < 4; ++j) {
                    unsigned* bhj = &bh[j >> 1][(j & 1) * 2];
                    unsigned* blj = &bl[j >> 1][(j & 1) * 2];
                    MMA16816(acc[i][j], ah[i], bhj);
                    MMA16816(acc[i][j], ah[i], blj);
                    MMA16816(acc[i][j], al[i], bhj);
                }
        }
    }

    float* C = P.C;
    ushortx* Ch = P.Ch;
    ushortx* Cl = P.Cl;
    const float* bias = P.bias;
#pragma unroll
    for (int i = 0; i < 4; ++i) {
        int r0 = bm + wm * 64 + i * 16 + g;
#pragma unroll
        for (int j = 0; j < 4; ++j) {
            int cn = bn + wn * 32 + j * 8 + 2 * t;
            float2 bv = make_float2(0.f, 0.f);
            if (bias) bv = *(const float2*)(bias + cn);
#pragma unroll
            for (int h = 0; h < 2; ++h) {
                int row = r0 + h * 8;
                if (row >= M) continue;
                float vx = acc[i][j][h * 2 + 0] + bv.x;
                float vy = acc[i][j][h * 2 + 1] + bv.y;
                if (relu) { vx = fmaxf(vx, 0.f); vy = fmaxf(vy, 0.f); }
                size_t o = (size_t)row * N + cn;
                if (C) *(float2*)(C + o) = make_float2(vx, vy);
                if (Ch) {
                    unsigned hh, ll;
                    bsplit(vx, vy, hh, ll);
                    *(unsigned*)(Ch + o) = hh;
                    *(unsigned*)(Cl + o) = ll;
                }
            }
        }
    }
}

// ---------------- fp32 SGEMM with fused log_softmax (N=40 head) ------------
#define BM 128
#define BN 64
#define BK 16
#define TM 8
#define TN 4
__global__ __launch_bounds__(256) void k_sgemm_lsm(
    const float* __restrict__ A, const float* __restrict__ B,
    const float* __restrict__ bias, float* __restrict__ C,
    int M, int N, int K) {
    __shared__ float As[BK][BM];
    __shared__ float Bs[BK][BN];
    const int tid = threadIdx.x;
    const int tx = tid & 15, ty = tid >> 4;
    const int bm = blockIdx.y * BM, bn = blockIdx.x * BN;
    float acc[TM][TN];
#pragma unroll
    for (int i = 0; i < TM; ++i)
#pragma unroll
        for (int j = 0; j < TN; ++j) acc[i][j] = 0.f;
    const int ar = tid >> 2, ac = (tid & 3) << 2;
    const int br = tid >> 4, bc = (tid & 15) << 2;
    for (int k0 = 0; k0 < K; k0 += BK) {
#pragma unroll
        for (int h = 0; h < 2; ++h) {
            int r = ar + h * 64, gr = bm + r;
            float4 v = make_float4(0.f, 0.f, 0.f, 0.f);
            if (gr < M) v = *(const float4*)(A + (size_t)gr * K + k0 + ac);
            As[ac + 0][r] = v.x; As[ac + 1][r] = v.y;
            As[ac + 2][r] = v.z; As[ac + 3][r] = v.w;
        }
        {
            int gc = bn + bc;
            float4 v = make_float4(0.f, 0.f, 0.f, 0.f);
            if (gc < N) v = *(const float4*)(B + (size_t)(k0 + br) * N + gc);
            *(float4*)&Bs[br][bc] = v;
        }
        __syncthreads();
#pragma unroll
        for (int kk = 0; kk < BK; ++kk) {
            float aF[TM], bF[TN];
#pragma unroll
            for (int i = 0; i < TM; ++i) aF[i] = As[kk][ty * TM + i];
#pragma unroll
            for (int j = 0; j < TN; ++j) bF[j] = Bs[kk][tx * TN + j];
#pragma unroll
            for (int i = 0; i < TM; ++i)
#pragma unroll
                for (int j = 0; j < TN; ++j) acc[i][j] = fmaf(aF[i], bF[j], acc[i][j]);
        }
        __syncthreads();
    }
    // fused bias + log_softmax over the row (all 40 cols live in the 16 tx
    // lanes of the same ty, consecutive lanes within a warp half)
    const int col0 = bn + tx * TN;
#pragma unroll
    for (int i = 0; i < TM; ++i) {
        int row = bm + ty * TM + i;
        float v[TN];
        float m = -3.4e38f;
#pragma unroll
        for (int j = 0; j < TN; ++j) {
            int c = col0 + j;
            v[j] = acc[i][j] + ((bias && c < N) ? bias[c] : 0.f);
            if (c < N) m = fmaxf(m, v[j]);
        }
#pragma unroll
        for (int o = 1; o < 16; o <<= 1) m = fmaxf(m, __shfl_xor_sync(0xffffffffu, m, o));
        float s = 0.f;
#pragma unroll
        for (int j = 0; j < TN; ++j)
            if (col0 + j < N) s += expf(v[j] - m);
#pragma unroll
        for (int o = 1; o < 16; o <<= 1) s += __shfl_xor_sync(0xffffffffu, s, o);
        float lse = m + logf(s);
        if (row < M) {
#pragma unroll
            for (int j = 0; j < TN; ++j) {
                int c = col0 + j;
                if (c < N) C[(size_t)row * N + c] = v[j] - lse;
            }
        }
    }
}

// ---------------- fused relu+residual+LayerNorm, state in bf16 hi/lo -------
__global__ void k_ln2(const float* __restrict__ ta,
                      ushortx* __restrict__ hah, ushortx* __restrict__ hal,
                      const float* __restrict__ ga_, const float* __restrict__ ba_,
                      const float* __restrict__ tp,
                      ushortx* __restrict__ hph, ushortx* __restrict__ hpl,
                      const float* __restrict__ gp_, const float* __restrict__ bp_) {
    int w = (blockIdx.x * blockDim.x + threadIdx.x) >> 5;
    int lane = threadIdx.x & 31;
    const float* t;
    ushortx *hh, *hl;
    const float *g, *b;
    if (w < AN) {
        t = ta; hh = hah; hl = hal; g = ga_; b = ba_;
    } else if (w < AN + PN) {
        w -= AN;
        t = tp; hh = hph; hl = hpl; g = gp_; b = bp_;
    } else return;
    const float4* t4 = (const float4*)(t + (size_t)w * HD);
    unsigned* hhu = (unsigned*)(hh + (size_t)w * HD);
    unsigned* hlu = (unsigned*)(hl + (size_t)w * HD);
    float4 x0 = t4[lane], x1 = t4[lane + 32];
    // residual from bf16 hi/lo reconstruct
    uint2 ph0 = *(uint2*)(hhu + lane * 2), ph1 = *(uint2*)(hhu + 64 + lane * 2);
    uint2 pl0 = *(uint2*)(hlu + lane * 2), pl1 = *(uint2*)(hlu + 64 + lane * 2);
    float p[8];
    float2 f, f2;
    f = b2f2(ph0.x); f2 = b2f2(pl0.x); p[0] = f.x + f2.x; p[1] = f.y + f2.y;
    f = b2f2(ph0.y); f2 = b2f2(pl0.y); p[2] = f.x + f2.x; p[3] = f.y + f2.y;
    f = b2f2(ph1.x); f2 = b2f2(pl1.x); p[4] = f.x + f2.x; p[5] = f.y + f2.y;
    f = b2f2(ph1.y); f2 = b2f2(pl1.y); p[6] = f.x + f2.x; p[7] = f.y + f2.y;
    float u[8];
    u[0] = fmaxf(x0.x, 0.f) + p[0]; u[1] = fmaxf(x0.y, 0.f) + p[1];
    u[2] = fmaxf(x0.z, 0.f) + p[2]; u[3] = fmaxf(x0.w, 0.f) + p[3];
    u[4] = fmaxf(x1.x, 0.f) + p[4]; u[5] = fmaxf(x1.y, 0.f) + p[5];
    u[6] = fmaxf(x1.z, 0.f) + p[6]; u[7] = fmaxf(x1.w, 0.f) + p[7];
    float s = 0.f;
#pragma unroll
    for (int i = 0; i < 8; ++i) s += u[i];
    s = warp_sum(s);
    float mu = s * (1.f / HD);
    float v = 0.f;
#pragma unroll
    for (int i = 0; i < 8; ++i) { float d = u[i] - mu; v += d * d; }
    v = warp_sum(v);
    float rstd = rsqrtf(v * (1.f / HD) + 1e-5f);
    const float4* g4 = (const float4*)g;
    const float4* b4 = (const float4*)b;
    float4 ga = g4[lane], gb = g4[lane + 32];
    float4 ba = b4[lane], bb = b4[lane + 32];
    float o[8];
    o[0] = (u[0] - mu) * rstd * ga.x + ba.x; o[1] = (u[1] - mu) * rstd * ga.y + ba.y;
    o[2] = (u[2] - mu) * rstd * ga.z + ba.z; o[3] = (u[3] - mu) * rstd * ga.w + ba.w;
    o[4] = (u[4] - mu) * rstd * gb.x + bb.x; o[5] = (u[5] - mu) * rstd * gb.y + bb.y;
    o[6] = (u[6] - mu) * rstd * gb.z + bb.z; o[7] = (u[7] - mu) * rstd * gb.w + bb.w;
    unsigned hv0, lv0, hv1, lv1;
    bsplit(o[0], o[1], hv0, lv0); bsplit(o[2], o[3], hv1, lv1);
    hhu[lane * 2] = hv0; hhu[lane * 2 + 1] = hv1;
    hlu[lane * 2] = lv0; hlu[lane * 2 + 1] = lv1;
    bsplit(o[4], o[5], hv0, lv0); bsplit(o[6], o[7], hv1, lv1);
    hhu[64 + lane * 2] = hv0; hhu[64 + lane * 2 + 1] = hv1;
    hlu[64 + lane * 2] = lv0; hlu[64 + lane * 2 + 1] = lv1;
}

// ---------------- host ----------------
static GProb mkprob(const ushortx* ah0, const ushortx* al0,
                    const ushortx* ah1, const ushortx* al1,
                    const ushortx* ah2, const ushortx* al2,
                    const ushortx* Bh, const ushortx* Bl,
                    const float* bias, float* C, ushortx* Ch, ushortx* Cl,
                    int M, int Ktot, int Kseg, int relu) {
    GProb p;
    p.ah0 = ah0; p.al0 = al0; p.ah1 = ah1; p.al1 = al1; p.ah2 = ah2; p.al2 = al2;
    p.Bh = Bh; p.Bl = Bl; p.bias = bias; p.C = C; p.Ch = Ch; p.Cl = Cl;
    p.M = M; p.Ktot = Ktot; p.Kseg = Kseg; p.relu = relu;
    return p;
}
static inline void bgemm2(const GProb& p0, const GProb& p1, int nz) {
    int my = (p0.M + 127) >> 7;
    if (nz == 2) { int m1 = (p1.M + 127) >> 7; if (m1 > my) my = m1; }
    dim3 grid(2, my, nz);
    k_bgemm<<<grid, 256, NSTAGE * STAGE>>>(p0, p1);
}

extern "C" void kernel_launch(void* const* d_in, const int* in_sizes, int n_in,
                              void* d_out, int out_size) {
    const float* x_author     = (const float*)d_in[0];
    const float* x_paper      = (const float*)d_in[1];
    const int*   e0_src       = (const int*)d_in[2];
    const int*   e0_dst       = (const int*)d_in[3];
    const int*   e1_src       = (const int*)d_in[4];
    const int*   e1_dst       = (const int*)d_in[5];
    const int*   e2_src       = (const int*)d_in[6];
    const int*   e2_dst       = (const int*)d_in[7];
    const float* emb_W_author = (const float*)d_in[8];
    const float* emb_b_author = (const float*)d_in[9];
    const float* emb_W_paper  = (const float*)d_in[10];
    const float* emb_b_paper  = (const float*)d_in[11];
    const float* W_self       = (const float*)d_in[12];
    const float* W_neigh      = (const float*)d_in[13];
    const float* b_conv       = (const float*)d_in[14];
    const float* ln_g_author  = (const float*)d_in[15];
    const float* ln_b_author  = (const float*)d_in[16];
    const float* ln_g_paper   = (const float*)d_in[17];
    const float* ln_b_paper   = (const float*)d_in[18];
    const float* pW1_author   = (const float*)d_in[19];
    const float* pb1_author   = (const float*)d_in[20];
    const float* pW2_author   = (const float*)d_in[21];
    const float* pb2_author   = (const float*)d_in[22];
    const float* pW1_paper    = (const float*)d_in[23];
    const float* pb1_paper    = (const float*)d_in[24];
    const float* pW2_paper    = (const float*)d_in[25];
    const float* pb2_paper    = (const float*)d_in[26];

    cudaFuncSetAttribute(k_bgemm, cudaFuncAttributeMaxDynamicSharedMemorySize, NSTAGE * STAGE);

    float *p_ta, *p_tp, *p_b01;
    ushortx *p_xah, *p_xal, *p_xph, *p_xpl, *p_hah, *p_hal, *p_hph, *p_hpl;
    ushortx *p_ag0h, *p_ag0l, *p_ag1h, *p_ag1l, *p_ag2h, *p_ag2l, *p_wh, *p_wl;
    int *p_deg, *p_off, *p_cur, *p_perm, *p_part;
    cudaGetSymbolAddress((void**)&p_ta, g_ta);
    cudaGetSymbolAddress((void**)&p_tp, g_tp);
    cudaGetSymbolAddress((void**)&p_b01, g_b01);
    cudaGetSymbolAddress((void**)&p_xah, g_xah);
    cudaGetSymbolAddress((void**)&p_xal, g_xal);
    cudaGetSymbolAddress((void**)&p_xph, g_xph);
    cudaGetSymbolAddress((void**)&p_xpl, g_xpl);
    cudaGetSymbolAddress((void**)&p_hah, g_hah);
    cudaGetSymbolAddress((void**)&p_hal, g_hal);
    cudaGetSymbolAddress((void**)&p_hph, g_hph);
    cudaGetSymbolAddress((void**)&p_hpl, g_hpl);
    cudaGetSymbolAddress((void**)&p_ag0h, g_ag0h);
    cudaGetSymbolAddress((void**)&p_ag0l, g_ag0l);
    cudaGetSymbolAddress((void**)&p_ag1h, g_ag1h);
    cudaGetSymbolAddress((void**)&p_ag1l, g_ag1l);
    cudaGetSymbolAddress((void**)&p_ag2h, g_ag2h);
    cudaGetSymbolAddress((void**)&p_ag2l, g_ag2l);
    cudaGetSymbolAddress((void**)&p_wh, g_wh);
    cudaGetSymbolAddress((void**)&p_wl, g_wl);
    cudaGetSymbolAddress((void**)&p_deg, g_deg);
    cudaGetSymbolAddress((void**)&p_off, g_off);
    cudaGetSymbolAddress((void**)&p_cur, g_cur);
    cudaGetSymbolAddress((void**)&p_perm, g_perm);
    cudaGetSymbolAddress((void**)&p_part, g_part);

    // ---- splits + bias combine + deg zeroing in ONE launch ----
    k_split_all<<<(NSPLIT_TOT + 255) / 256, 256>>>(
        x_author, x_paper, emb_W_author, emb_W_paper, W_self, W_neigh,
        pW1_author, pW1_paper, pW2_paper, b_conv,
        p_wh, p_wl, p_xah, p_xal, p_xph, p_xpl, p_b01, p_deg);

    // ---- CSR build ----
    k_hist3<<<(3 * EN + 255) / 256, 256>>>(e0_dst, e1_dst, e2_dst, p_deg);
    k_scan_sum<<<NBT, 1024>>>(p_deg, p_part);
    k_scan_top<<<1, 32>>>(p_part, p_off);
    k_scan_apply<<<NBT, 1024>>>(p_deg, p_part, p_off, p_cur);
    k_fill3<<<(3 * EN + 255) / 256, 256>>>(e0_src, e0_dst, e1_src, e1_dst,
                                           e2_src, e2_dst, p_cur, p_perm);

    // ---- embeddings: splits only (no fp32 h) ----
    bgemm2(mkprob(p_xah, p_xal, 0, 0, 0, 0, p_wh + WOFF_EMBA, p_wl + WOFF_EMBA,
                  emb_b_author, 0, p_hah, p_hal, AN, DIN, DIN, 0),
           mkprob(p_xph, p_xpl, 0, 0, 0, 0, p_wh + WOFF_EMBP, p_wl + WOFF_EMBP,
                  emb_b_paper, 0, p_hph, p_hpl, PN, DIN, DIN, 0), 2);

    // ---- 2 SAGE layers ----
    const int WPO[2] = {WOFF_WP0, WOFF_WP1};
    const int WAO[2] = {WOFF_WA0, WOFF_WA1};
    const int NWARP_AGG = 2 * PN + AN;
    for (int l = 0; l < 2; ++l) {
        const float* bc = b_conv + (size_t)l * 3 * HD;
        k_agg3<<<(NWARP_AGG * 32 + 127) / 128, 128>>>(
            p_hah, p_hal, p_hph, p_hpl, p_off, p_perm,
            p_ag0h, p_ag0l, p_ag1h, p_ag1l, p_ag2h, p_ag2l);
        bgemm2(mkprob(p_hph, p_hpl, p_ag0h, p_ag0l, p_ag1h, p_ag1l,
                      p_wh + WPO[l], p_wl + WPO[l], p_b01 + l * HD,
                      p_tp, 0, 0, PN, 3 * HD, HD, 0),
               mkprob(p_hah, p_hal, p_ag2h, p_ag2l, 0, 0,
                      p_wh + WAO[l], p_wl + WAO[l], bc + 2 * HD,
                      p_ta, 0, 0, AN, 2 * HD, HD, 0), 2);
        k_ln2<<<((AN + PN) * 32 + 127) / 128, 128>>>(
            p_ta, p_hah, p_hal, ln_g_author, ln_b_author,
            p_tp, p_hph, p_hpl, ln_g_paper, ln_b_paper);
    }

    // ---- output heads ----
    float* out = (float*)d_out;
    bgemm2(mkprob(p_hah, p_hal, 0, 0, 0, 0, p_wh + WOFF_P1A, p_wl + WOFF_P1A,
                  pb1_author, p_ta, 0, 0, AN, HD, HD, 1),
           mkprob(p_hph, p_hpl, 0, 0, 0, 0, p_wh + WOFF_P1P, p_wl + WOFF_P1P,
                  pb1_paper, 0, p_ag0h, p_ag0l, PN, HD, HD, 1), 2);
    bgemm2(mkprob(p_ag0h, p_ag0l, 0, 0, 0, 0, p_wh + WOFF_P2P, p_wl + WOFF_P2P,
                  pb2_paper, out + (size_t)AN * CN, 0, 0, PN, HD, HD, 0),
           mkprob(0, 0, 0, 0, 0, 0, 0, 0, 0, 0, 0, 0, 0, HD, HD, 0), 1);
    {
        dim3 grid((CN + BN - 1) / BN, (AN + BM - 1) / BM);
        k_sgemm_lsm<<<grid, 256>>>(p_ta, pW2_author, pb2_author, out, AN, CN, HD);
    }
}

// round 15
// speedup vs baseline: 1.0981x; 1.0181x over previous
#include <cuda_runtime.h>
#include <cuda_bf16.h>
#include <math.h>

#define AN 50000
#define PN 100000
#define DIN 128
#define HD 256
#define CN 40
#define EN 300000

typedef unsigned short ushortx;

__device__ float g_ta[(size_t)AN * HD];
__device__ float g_tp[(size_t)PN * HD];
__device__ float g_b01[2 * HD];
__device__ ushortx g_xah[(size_t)AN * DIN], g_xal[(size_t)AN * DIN];
__device__ ushortx g_xph[(size_t)PN * DIN], g_xpl[(size_t)PN * DIN];
__device__ ushortx g_hah[(size_t)AN * HD],  g_hal[(size_t)AN * HD];
__device__ ushortx g_hph[(size_t)PN * HD],  g_hpl[(size_t)PN * HD];
__device__ ushortx g_ag0h[(size_t)PN * HD], g_ag0l[(size_t)PN * HD];
__device__ ushortx g_ag1h[(size_t)PN * HD], g_ag1l[(size_t)PN * HD];
__device__ ushortx g_ag2h[(size_t)AN * HD], g_ag2l[(size_t)AN * HD];
#define WOFF_EMBA 0
#define WOFF_EMBP (WOFF_EMBA + 128 * 256)
#define WOFF_WP0  (WOFF_EMBP + 128 * 256)
#define WOFF_WA0  (WOFF_WP0 + 768 * 256)
#define WOFF_WP1  (WOFF_WA0 + 512 * 256)
#define WOFF_WA1  (WOFF_WP1 + 768 * 256)
#define WOFF_P1A  (WOFF_WA1 + 512 * 256)
#define WOFF_P1P  (WOFF_P1A + 256 * 256)
#define WOFF_P2P  (WOFF_P1P + 256 * 256)
#define WTOT      (WOFF_P2P + 256 * 256)
__device__ ushortx g_wh[WTOT], g_wl[WTOT];
#define NB_P 98
#define NB_A 49
#define NBT (NB_P + NB_P + NB_A)
__device__ int g_deg[3 * PN];
__device__ int g_off[3 * (PN + 1)];
__device__ int g_cur[3 * PN];
__device__ int g_perm[3 * EN];
__device__ int g_part[NBT];

// ---------------- helpers ----------------
__device__ __forceinline__ unsigned smem_u32(const void* p) {
    unsigned a;
    asm("{ .reg .u64 t; cvta.to.shared.u64 t, %1; cvt.u32.u64 %0, t; }" : "=r"(a) : "l"(p));
    return a;
}
__device__ __forceinline__ void cp16(unsigned dst, const void* src, int n) {
    asm volatile("cp.async.cg.shared.global [%0], [%1], 16, %2;" :: "r"(dst), "l"(src), "r"(n));
}
#define CP_COMMIT() asm volatile("cp.async.commit_group;" ::: "memory")
#define CP_WAIT0()  asm volatile("cp.async.wait_group 0;" ::: "memory")

__device__ __forceinline__ void bsplit(float x, float y, unsigned& h, unsigned& l) {
    __nv_bfloat162 hb = __floats2bfloat162_rn(x, y);
    float rx = x - __bfloat162float(hb.x);
    float ry = y - __bfloat162float(hb.y);
    __nv_bfloat162 lb = __floats2bfloat162_rn(rx, ry);
    h = *(unsigned*)&hb;
    l = *(unsigned*)&lb;
}
__device__ __forceinline__ float2 b2f2(unsigned u) {
    __nv_bfloat162 t = *(__nv_bfloat162*)&u;
    return make_float2(__bfloat162float(t.x), __bfloat162float(t.y));
}
__device__ __forceinline__ void split4(float4 v, uint2& h, uint2& l) {
    unsigned h0, l0, h1, l1;
    bsplit(v.x, v.y, h0, l0);
    bsplit(v.z, v.w, h1, l1);
    h = make_uint2(h0, h1);
    l = make_uint2(l0, l1);
}
#define MMA16816(c, a, b) \
    asm volatile("mma.sync.aligned.m16n8k16.row.col.f32.bf16.bf16.f32 " \
        "{%0,%1,%2,%3},{%4,%5,%6,%7},{%8,%9},{%0,%1,%2,%3};" \
        : "+f"((c)[0]), "+f"((c)[1]), "+f"((c)[2]), "+f"((c)[3]) \
        : "r"((a)[0]), "r"((a)[1]), "r"((a)[2]), "r"((a)[3]), "r"((b)[0]), "r"((b)[1]))
#define LDSM4(r, addr) \
    asm volatile("ldmatrix.sync.aligned.m8n8.x4.shared.b16 {%0,%1,%2,%3},[%4];" \
        : "=r"((r)[0]), "=r"((r)[1]), "=r"((r)[2]), "=r"((r)[3]) : "r"(addr))
#define LDSM4T(r, addr) \
    asm volatile("ldmatrix.sync.aligned.m8n8.x4.trans.shared.b16 {%0,%1,%2,%3},[%4];" \
        : "=r"((r)[0]), "=r"((r)[1]), "=r"((r)[2]), "=r"((r)[3]) : "r"(addr))

__device__ __forceinline__ float warp_sum(float v) {
#pragma unroll
    for (int o = 16; o; o >>= 1) v += __shfl_xor_sync(0xffffffffu, v, o);
    return v;
}
__device__ __forceinline__ int warp_sumi(int v) {
#pragma unroll
    for (int o = 16; o; o >>= 1) v += __shfl_xor_sync(0xffffffffu, v, o);
    return v;
}

// ---------------- mega split kernel, float4-vectorized ----------------
#define NXA (AN * DIN)
#define NXP (PN * DIN)
#define NS4 ((NXA + NXP + WTOT + 512 + 3 * PN) / 4)
#define NXA4 (NXA / 4)
#define NXP4 (NXP / 4)
#define WT4  (WTOT / 4)

__global__ void k_split_all(
    const float* __restrict__ x_author, const float* __restrict__ x_paper,
    const float* __restrict__ emb_W_author, const float* __restrict__ emb_W_paper,
    const float* __restrict__ W_self, const float* __restrict__ W_neigh,
    const float* __restrict__ pW1_author, const float* __restrict__ pW1_paper,
    const float* __restrict__ pW2_paper, const float* __restrict__ b_conv,
    ushortx* __restrict__ wh, ushortx* __restrict__ wl,
    ushortx* __restrict__ xah, ushortx* __restrict__ xal,
    ushortx* __restrict__ xph, ushortx* __restrict__ xpl,
    float* __restrict__ b01, int* __restrict__ deg) {
    int i = blockIdx.x * blockDim.x + threadIdx.x;
    if (i >= NS4) return;
    if (i < NXA4) {
        float4 v = *(const float4*)(x_author + i * 4);
        uint2 h, l;
        split4(v, h, l);
        *(uint2*)(xah + i * 4) = h;
        *(uint2*)(xal + i * 4) = l;
        return;
    }
    i -= NXA4;
    if (i < NXP4) {
        float4 v = *(const float4*)(x_paper + i * 4);
        uint2 h, l;
        split4(v, h, l);
        *(uint2*)(xph + i * 4) = h;
        *(uint2*)(xpl + i * 4) = l;
        return;
    }
    i -= NXP4;
    if (i < WT4) {
        const int j = i * 4;  // element index, 4-aligned; all regions 4-aligned
        const int Q = 65536;
        float4 v;
        if (j < Q) {
            v = (j < Q / 2) ? *(const float4*)(emb_W_author + j)
                            : *(const float4*)(emb_W_paper + j - Q / 2);
        } else if (j < 2 * Q) {
            int r = j - Q;
            float4 a = *(const float4*)(W_self + r);
            float4 b = *(const float4*)(W_self + Q + r);
            v = make_float4(a.x + b.x, a.y + b.y, a.z + b.z, a.w + b.w);
        } else if (j < 3 * Q)  v = *(const float4*)(W_neigh + j - 2 * Q);
        else if (j < 4 * Q)    v = *(const float4*)(W_neigh + Q + j - 3 * Q);
        else if (j < 5 * Q)    v = *(const float4*)(W_self + 2 * Q + j - 4 * Q);
        else if (j < 6 * Q)    v = *(const float4*)(W_neigh + 2 * Q + j - 5 * Q);
        else if (j < 7 * Q) {
            int r = j - 6 * Q;
            float4 a = *(const float4*)(W_self + 3 * Q + r);
            float4 b = *(const float4*)(W_self + 4 * Q + r);
            v = make_float4(a.x + b.x, a.y + b.y, a.z + b.z, a.w + b.w);
        } else if (j < 8 * Q)  v = *(const float4*)(W_neigh + 3 * Q + j - 7 * Q);
        else if (j < 9 * Q)    v = *(const float4*)(W_neigh + 4 * Q + j - 8 * Q);
        else if (j < 10 * Q)   v = *(const float4*)(W_self + 5 * Q + j - 9 * Q);
        else if (j < 11 * Q)   v = *(const float4*)(W_neigh + 5 * Q + j - 10 * Q);
        else if (j < 12 * Q)   v = *(const float4*)(pW1_author + j - 11 * Q);
        else if (j < 13 * Q)   v = *(const float4*)(pW1_paper + j - 12 * Q);
        else                   v = *(const float4*)(pW2_paper + j - 13 * Q);
        uint2 h, l;
        split4(v, h, l);
        *(uint2*)(wh + j) = h;
        *(uint2*)(wl + j) = l;
        return;
    }
    i -= WT4;
    if (i < 128) {  // 512 bias elements / 4
        int j = i * 4;
        int l = j >> 8, c = j & 255;
#pragma unroll
        for (int q = 0; q < 4; ++q)
            b01[j + q] = b_conv[l * 768 + c + q] + b_conv[l * 768 + 256 + c + q];
        return;
    }
    i -= 128;
    *(int4*)(deg + i * 4) = make_int4(0, 0, 0, 0);
}

// ---------------- CSR build ----------------
__global__ void k_hist3(const int* __restrict__ d0, const int* __restrict__ d1,
                        const int* __restrict__ d2, int* __restrict__ deg) {
    int i = blockIdx.x * blockDim.x + threadIdx.x;
    if (i >= 3 * EN) return;
    int t = i / EN, k = i - t * EN;
    const int* d = (t == 0) ? d0 : ((t == 1) ? d1 : d2);
    atomicAdd(&deg[t * PN + d[k]], 1);
}
__device__ __forceinline__ void scan_block_coords(int b, int& t, int& blk, int& nd) {
    if (b < NB_P)            { t = 0; blk = b;              nd = PN; }
    else if (b < 2 * NB_P)   { t = 1; blk = b - NB_P;       nd = PN; }
    else                     { t = 2; blk = b - 2 * NB_P;   nd = AN; }
}
__global__ void k_scan_sum(const int* __restrict__ deg, int* __restrict__ part) {
    __shared__ int sh[32];
    int t, blk, nd;
    scan_block_coords(blockIdx.x, t, blk, nd);
    int i = blk * 1024 + threadIdx.x;
    int v = (i < nd) ? deg[t * PN + i] : 0;
    v = warp_sumi(v);
    if ((threadIdx.x & 31) == 0) sh[threadIdx.x >> 5] = v;
    __syncthreads();
    if (threadIdx.x < 32) {
        int x = sh[threadIdx.x];
        x = warp_sumi(x);
        if (threadIdx.x == 0) part[blockIdx.x] = x;
    }
}
// 3 warps, one per edge type: chunked inclusive warp-scan with running carry
__global__ void k_scan_top(int* __restrict__ part, int* __restrict__ off) {
    int w = threadIdx.x >> 5, lane = threadIdx.x & 31;
    if (w >= 3) return;
    int base = (w == 0) ? 0 : ((w == 1) ? NB_P : 2 * NB_P);
    int n = (w == 2) ? NB_A : NB_P;
    int nd = (w == 2) ? AN : PN;
    int run = 0;
    for (int b0 = 0; b0 < n; b0 += 32) {
        int idx = b0 + lane;
        int orig = (idx < n) ? part[base + idx] : 0;
        int v = orig;
#pragma unroll
        for (int o = 1; o < 32; o <<= 1) {
            int t = __shfl_up_sync(0xffffffffu, v, o);
            if (lane >= o) v += t;
        }
        if (idx < n) part[base + idx] = run + v - orig;  // exclusive
        run += __shfl_sync(0xffffffffu, v, 31);
    }
    if (lane == 0) off[w * (PN + 1) + nd] = run;
}
__global__ void k_scan_apply(const int* __restrict__ deg, const int* __restrict__ part,
                             int* __restrict__ off, int* __restrict__ cur) {
    __shared__ int sh[1024];
    int t, blk, nd;
    scan_block_coords(blockIdx.x, t, blk, nd);
    int i = blk * 1024 + threadIdx.x;
    int v = (i < nd) ? deg[t * PN + i] : 0;
    sh[threadIdx.x] = v;
    __syncthreads();
#pragma unroll
    for (int d = 1; d < 1024; d <<= 1) {
        int x = (threadIdx.x >= d) ? sh[threadIdx.x - d] : 0;
        __syncthreads();
        sh[threadIdx.x] += x;
        __syncthreads();
    }
    if (i < nd) {
        int o = part[blockIdx.x] + sh[threadIdx.x] - v;
        off[t * (PN + 1) + i] = o;
        cur[t * PN + i] = o;
    }
}
__global__ void k_fill3(const int* __restrict__ s0, const int* __restrict__ d0,
                        const int* __restrict__ s1, const int* __restrict__ d1,
                        const int* __restrict__ s2, const int* __restrict__ d2,
                        int* __restrict__ cur, int* __restrict__ perm) {
    int i = blockIdx.x * blockDim.x + threadIdx.x;
    if (i >= 3 * EN) return;
    int t = i / EN, k = i - t * EN;
    const int* s = (t == 0) ? s0 : ((t == 1) ? s1 : s2);
    const int* d = (t == 0) ? d0 : ((t == 1) ? d1 : d2);
    int slot = atomicAdd(&cur[t * PN + d[k]], 1);
    perm[t * EN + slot] = s[k];
}

// ---------------- 3 mean aggregations, gather from bf16 hi/lo state --------
__global__ void k_agg3(const ushortx* __restrict__ hah, const ushortx* __restrict__ hal,
                       const ushortx* __restrict__ hph, const ushortx* __restrict__ hpl,
                       const int* __restrict__ off, const int* __restrict__ perm,
                       ushortx* __restrict__ ag0h, ushortx* __restrict__ ag0l,
                       ushortx* __restrict__ ag1h, ushortx* __restrict__ ag1l,
                       ushortx* __restrict__ ag2h, ushortx* __restrict__ ag2l) {
    int w = (blockIdx.x * blockDim.x + threadIdx.x) >> 5;
    int lane = threadIdx.x & 31;
    const ushortx *sh_, *sl_;
    const int* of;
    const int* pm;
    ushortx *oh, *ol;
    if (w < PN) {
        sh_ = hah; sl_ = hal; of = off; pm = perm; oh = ag0h; ol = ag0l;
    } else if (w < 2 * PN) {
        w -= PN;
        sh_ = hph; sl_ = hpl; of = off + (PN + 1); pm = perm + EN; oh = ag1h; ol = ag1l;
    } else if (w < 2 * PN + AN) {
        w -= 2 * PN;
        sh_ = hph; sl_ = hpl; of = off + 2 * (PN + 1); pm = perm + 2 * EN; oh = ag2h; ol = ag2l;
    } else return;
    int s = of[w], e = of[w + 1];
    float a[8];
#pragma unroll
    for (int q = 0; q < 8; ++q) a[q] = 0.f;
    for (int i = s; i < e; ++i) {
        size_t row = (size_t)pm[i] * HD;
        const uint2* rh = (const uint2*)(sh_ + row);
        const uint2* rl = (const uint2*)(sl_ + row);
        uint2 h0 = __ldg(&rh[lane]), h1 = __ldg(&rh[lane + 32]);
        uint2 l0 = __ldg(&rl[lane]), l1 = __ldg(&rl[lane + 32]);
        float2 f;
        f = b2f2(h0.x); a[0] += f.x; a[1] += f.y;
        f = b2f2(h0.y); a[2] += f.x; a[3] += f.y;
        f = b2f2(h1.x); a[4] += f.x; a[5] += f.y;
        f = b2f2(h1.y); a[6] += f.x; a[7] += f.y;
        f = b2f2(l0.x); a[0] += f.x; a[1] += f.y;
        f = b2f2(l0.y); a[2] += f.x; a[3] += f.y;
        f = b2f2(l1.x); a[4] += f.x; a[5] += f.y;
        f = b2f2(l1.y); a[6] += f.x; a[7] += f.y;
    }
    float inv = (e > s) ? 1.f / (float)(e - s) : 0.f;
#pragma unroll
    for (int q = 0; q < 8; ++q) a[q] *= inv;
    unsigned h0, l0, h1, l1;
    unsigned* ohu = (unsigned*)(oh + (size_t)w * HD);
    unsigned* olu = (unsigned*)(ol + (size_t)w * HD);
    bsplit(a[0], a[1], h0, l0); bsplit(a[2], a[3], h1, l1);
    ohu[lane * 2] = h0; ohu[lane * 2 + 1] = h1;
    olu[lane * 2] = l0; olu[lane * 2 + 1] = l1;
    bsplit(a[4], a[5], h0, l0); bsplit(a[6], a[7], h1, l1);
    ohu[64 + lane * 2] = h0; ohu[64 + lane * 2 + 1] = h1;
    olu[64 + lane * 2] = l0; olu[64 + lane * 2 + 1] = l1;
}

// ---------------- bf16 HMMA 3-split GEMM, 2-stage, occ=2, paired via z -----
#define A_ST 80
#define B_ST 272
#define OFF_AL 10240
#define OFF_BH 20480
#define OFF_BL 29184
#define STAGE 37888
#define NSTAGE 2

struct GProb {
    const ushortx *ah0, *al0, *ah1, *al1, *ah2, *al2, *Bh, *Bl;
    const float* bias;
    float* C;
    ushortx *Ch, *Cl;
    int M, Ktot, Kseg, relu;
};

__global__ __launch_bounds__(256, 2) void k_bgemm(GProb p0, GProb p1) {
    extern __shared__ char smc[];
    const GProb& P = (blockIdx.z == 0) ? p0 : p1;
    const int bm = blockIdx.y * 128;
    const int M = P.M;
    if (bm >= M) return;
    const ushortx* ah0 = P.ah0; const ushortx* al0 = P.al0;
    const ushortx* ah1 = P.ah1; const ushortx* al1 = P.al1;
    const ushortx* ah2 = P.ah2; const ushortx* al2 = P.al2;
    const ushortx* Bh = P.Bh;   const ushortx* Bl = P.Bl;
    const int Ktot = P.Ktot, Kseg = P.Kseg, relu = P.relu;
    const int N = 256;

    const int tid = threadIdx.x;
    const int lane = tid & 31;
    const int warp = tid >> 5;
    const int g = lane >> 2;
    const int t = lane & 3;
    const int wm = warp & 1;
    const int wn = warp >> 1;
    const int bn = blockIdx.x * 128;
    const unsigned sbase = smem_u32(smc);
    const int NIT = Ktot >> 5;
    const int segC = Kseg >> 5;

    float acc[4][4][4];
#pragma unroll
    for (int i = 0; i < 4; ++i)
#pragma unroll
        for (int j = 0; j < 4; ++j)
#pragma unroll
            for (int q = 0; q < 4; ++q) acc[i][j][q] = 0.f;

    const int ca = tid * 2;
    const int arow0 = ca >> 2, ac0 = ca & 3;
    const int arow1 = (ca + 1) >> 2, ac1 = (ca + 1) & 3;
    const int brow0 = ca >> 4, bc0 = ca & 15;
    const int brow1 = (ca + 1) >> 4, bc1 = (ca + 1) & 15;

    auto issue = [&](int it) {
        int seg = it / segC;
        int kloc = (it - seg * segC) << 5;
        const ushortx* pah = (seg == 0) ? ah0 : ((seg == 1) ? ah1 : ah2);
        const ushortx* pal = (seg == 0) ? al0 : ((seg == 1) ? al1 : al2);
        unsigned sa = sbase + (it & 1) * STAGE;
        int gr0 = bm + arow0, gr1 = bm + arow1;
        int ok0 = gr0 < M ? 16 : 0, ok1 = gr1 < M ? 16 : 0;
        size_t off0 = (size_t)(gr0 < M ? gr0 : 0) * Kseg + kloc + ac0 * 8;
        size_t off1 = (size_t)(gr1 < M ? gr1 : 0) * Kseg + kloc + ac1 * 8;
        cp16(sa + arow0 * A_ST + ac0 * 16, pah + off0, ok0);
        cp16(sa + arow1 * A_ST + ac1 * 16, pah + off1, ok1);
        cp16(sa + OFF_AL + arow0 * A_ST + ac0 * 16, pal + off0, ok0);
        cp16(sa + OFF_AL + arow1 * A_ST + ac1 * 16, pal + off1, ok1);
        int kg = it << 5;
        size_t bo0 = (size_t)(kg + brow0) * N + bn + bc0 * 8;
        size_t bo1 = (size_t)(kg + brow1) * N + bn + bc1 * 8;
        cp16(sa + OFF_BH + brow0 * B_ST + bc0 * 16, Bh + bo0, 16);
        cp16(sa + OFF_BH + brow1 * B_ST + bc1 * 16, Bh + bo1, 16);
        cp16(sa + OFF_BL + brow0 * B_ST + bc0 * 16, Bl + bo0, 16);
        cp16(sa + OFF_BL + brow1 * B_ST + bc1 * 16, Bl + bo1, 16);
        CP_COMMIT();
    };

    issue(0);
    for (int it = 0; it < NIT; ++it) {
        CP_WAIT0();
        __syncthreads();
        if (it + 1 < NIT) issue(it + 1);
        const unsigned sa = sbase + (it & 1) * STAGE;
#pragma unroll
        for (int kk = 0; kk < 2; ++kk) {
            unsigned ah[4][4], al[4][4], bh[2][4], bl[2][4];
            unsigned abase = sa + (wm * 64 + (lane & 15)) * A_ST + kk * 32 + ((lane >> 4) << 4);
#pragma unroll
            for (int i = 0; i < 4; ++i) {
                LDSM4(ah[i], abase + i * (16 * A_ST));
                LDSM4(al[i], abase + i * (16 * A_ST) + OFF_AL);
            }
            unsigned bbase = sa + OFF_BH + (kk * 16 + (lane & 15)) * B_ST +
                             (wn * 32 + ((lane >> 4) << 3)) * 2;
#pragma unroll
            for (int p = 0; p < 2; ++p) {
                LDSM4T(bh[p], bbase + p * 32);
                LDSM4T(bl[p], bbase + p * 32 + (OFF_BL - OFF_BH));
            }
#pragma unroll
            for (int i = 0; i < 4; ++i)
#pragma unroll
                for (int j = 0; j < 4; ++j) {
                    unsigned* bhj = &bh[j >> 1][(j & 1) * 2];
                    unsigned* blj = &bl[j >> 1][(j & 1) * 2];
                    MMA16816(acc[i][j], ah[i], bhj);
                    MMA16816(acc[i][j], ah[i], blj);
                    MMA16816(acc[i][j], al[i], bhj);
                }
        }
    }

    float* C = P.C;
    ushortx* Ch = P.Ch;
    ushortx* Cl = P.Cl;
    const float* bias = P.bias;
#pragma unroll
    for (int i = 0; i < 4; ++i) {
        int r0 = bm + wm * 64 + i * 16 + g;
#pragma unroll
        for (int j = 0; j < 4; ++j) {
            int cn = bn + wn * 32 + j * 8 + 2 * t;
            float2 bv = make_float2(0.f, 0.f);
            if (bias) bv = *(const float2*)(bias + cn);
#pragma unroll
            for (int h = 0; h < 2; ++h) {
                int row = r0 + h * 8;
                if (row >= M) continue;
                float vx = acc[i][j][h * 2 + 0] + bv.x;
                float vy = acc[i][j][h * 2 + 1] + bv.y;
                if (relu) { vx = fmaxf(vx, 0.f); vy = fmaxf(vy, 0.f); }
                size_t o = (size_t)row * N + cn;
                if (C) *(float2*)(C + o) = make_float2(vx, vy);
                if (Ch) {
                    unsigned hh, ll;
                    bsplit(vx, vy, hh, ll);
                    *(unsigned*)(Ch + o) = hh;
                    *(unsigned*)(Cl + o) = ll;
                }
            }
        }
    }
}

// ---------------- fp32 SGEMM with fused log_softmax (N=40 head) ------------
#define BM 128
#define BN 64
#define BK 16
#define TM 8
#define TN 4
__global__ __launch_bounds__(256) void k_sgemm_lsm(
    const float* __restrict__ A, const float* __restrict__ B,
    const float* __restrict__ bias, float* __restrict__ C,
    int M, int N, int K) {
    __shared__ float As[BK][BM];
    __shared__ float Bs[BK][BN];
    const int tid = threadIdx.x;
    const int tx = tid & 15, ty = tid >> 4;
    const int bm = blockIdx.y * BM, bn = blockIdx.x * BN;
    float acc[TM][TN];
#pragma unroll
    for (int i = 0; i < TM; ++i)
#pragma unroll
        for (int j = 0; j < TN; ++j) acc[i][j] = 0.f;
    const int ar = tid >> 2, ac = (tid & 3) << 2;
    const int br = tid >> 4, bc = (tid & 15) << 2;
    for (int k0 = 0; k0 < K; k0 += BK) {
#pragma unroll
        for (int h = 0; h < 2; ++h) {
            int r = ar + h * 64, gr = bm + r;
            float4 v = make_float4(0.f, 0.f, 0.f, 0.f);
            if (gr < M) v = *(const float4*)(A + (size_t)gr * K + k0 + ac);
            As[ac + 0][r] = v.x; As[ac + 1][r] = v.y;
            As[ac + 2][r] = v.z; As[ac + 3][r] = v.w;
        }
        {
            int gc = bn + bc;
            float4 v = make_float4(0.f, 0.f, 0.f, 0.f);
            if (gc < N) v = *(const float4*)(B + (size_t)(k0 + br) * N + gc);
            *(float4*)&Bs[br][bc] = v;
        }
        __syncthreads();
#pragma unroll
        for (int kk = 0; kk < BK; ++kk) {
            float aF[TM], bF[TN];
#pragma unroll
            for (int i = 0; i < TM; ++i) aF[i] = As[kk][ty * TM + i];
#pragma unroll
            for (int j = 0; j < TN; ++j) bF[j] = Bs[kk][tx * TN + j];
#pragma unroll
            for (int i = 0; i < TM; ++i)
#pragma unroll
                for (int j = 0; j < TN; ++j) acc[i][j] = fmaf(aF[i], bF[j], acc[i][j]);
        }
        __syncthreads();
    }
    const int col0 = bn + tx * TN;
#pragma unroll
    for (int i = 0; i < TM; ++i) {
        int row = bm + ty * TM + i;
        float v[TN];
        float m = -3.4e38f;
#pragma unroll
        for (int j = 0; j < TN; ++j) {
            int c = col0 + j;
            v[j] = acc[i][j] + ((bias && c < N) ? bias[c] : 0.f);
            if (c < N) m = fmaxf(m, v[j]);
        }
#pragma unroll
        for (int o = 1; o < 16; o <<= 1) m = fmaxf(m, __shfl_xor_sync(0xffffffffu, m, o));
        float s = 0.f;
#pragma unroll
        for (int j = 0; j < TN; ++j)
            if (col0 + j < N) s += expf(v[j] - m);
#pragma unroll
        for (int o = 1; o < 16; o <<= 1) s += __shfl_xor_sync(0xffffffffu, s, o);
        float lse = m + logf(s);
        if (row < M) {
#pragma unroll
            for (int j = 0; j < TN; ++j) {
                int c = col0 + j;
                if (c < N) C[(size_t)row * N + c] = v[j] - lse;
            }
        }
    }
}

// ---------------- fused relu+residual+LayerNorm, state in bf16 hi/lo -------
__global__ void k_ln2(const float* __restrict__ ta,
                      ushortx* __restrict__ hah, ushortx* __restrict__ hal,
                      const float* __restrict__ ga_, const float* __restrict__ ba_,
                      const float* __restrict__ tp,
                      ushortx* __restrict__ hph, ushortx* __restrict__ hpl,
                      const float* __restrict__ gp_, const float* __restrict__ bp_) {
    int w = (blockIdx.x * blockDim.x + threadIdx.x) >> 5;
    int lane = threadIdx.x & 31;
    const float* t;
    ushortx *hh, *hl;
    const float *g, *b;
    if (w < AN) {
        t = ta; hh = hah; hl = hal; g = ga_; b = ba_;
    } else if (w < AN + PN) {
        w -= AN;
        t = tp; hh = hph; hl = hpl; g = gp_; b = bp_;
    } else return;
    const float4* t4 = (const float4*)(t + (size_t)w * HD);
    unsigned* hhu = (unsigned*)(hh + (size_t)w * HD);
    unsigned* hlu = (unsigned*)(hl + (size_t)w * HD);
    float4 x0 = t4[lane], x1 = t4[lane + 32];
    uint2 ph0 = *(uint2*)(hhu + lane * 2), ph1 = *(uint2*)(hhu + 64 + lane * 2);
    uint2 pl0 = *(uint2*)(hlu + lane * 2), pl1 = *(uint2*)(hlu + 64 + lane * 2);
    float p[8];
    float2 f, f2;
    f = b2f2(ph0.x); f2 = b2f2(pl0.x); p[0] = f.x + f2.x; p[1] = f.y + f2.y;
    f = b2f2(ph0.y); f2 = b2f2(pl0.y); p[2] = f.x + f2.x; p[3] = f.y + f2.y;
    f = b2f2(ph1.x); f2 = b2f2(pl1.x); p[4] = f.x + f2.x; p[5] = f.y + f2.y;
    f = b2f2(ph1.y); f2 = b2f2(pl1.y); p[6] = f.x + f2.x; p[7] = f.y + f2.y;
    float u[8];
    u[0] = fmaxf(x0.x, 0.f) + p[0]; u[1] = fmaxf(x0.y, 0.f) + p[1];
    u[2] = fmaxf(x0.z, 0.f) + p[2]; u[3] = fmaxf(x0.w, 0.f) + p[3];
    u[4] = fmaxf(x1.x, 0.f) + p[4]; u[5] = fmaxf(x1.y, 0.f) + p[5];
    u[6] = fmaxf(x1.z, 0.f) + p[6]; u[7] = fmaxf(x1.w, 0.f) + p[7];
    float s = 0.f;
#pragma unroll
    for (int i = 0; i < 8; ++i) s += u[i];
    s = warp_sum(s);
    float mu = s * (1.f / HD);
    float v = 0.f;
#pragma unroll
    for (int i = 0; i < 8; ++i) { float d = u[i] - mu; v += d * d; }
    v = warp_sum(v);
    float rstd = rsqrtf(v * (1.f / HD) + 1e-5f);
    const float4* g4 = (const float4*)g;
    const float4* b4 = (const float4*)b;
    float4 ga = g4[lane], gb = g4[lane + 32];
    float4 ba = b4[lane], bb = b4[lane + 32];
    float o[8];
    o[0] = (u[0] - mu) * rstd * ga.x + ba.x; o[1] = (u[1] - mu) * rstd * ga.y + ba.y;
    o[2] = (u[2] - mu) * rstd * ga.z + ba.z; o[3] = (u[3] - mu) * rstd * ga.w + ba.w;
    o[4] = (u[4] - mu) * rstd * gb.x + bb.x; o[5] = (u[5] - mu) * rstd * gb.y + bb.y;
    o[6] = (u[6] - mu) * rstd * gb.z + bb.z; o[7] = (u[7] - mu) * rstd * gb.w + bb.w;
    unsigned hv0, lv0, hv1, lv1;
    bsplit(o[0], o[1], hv0, lv0); bsplit(o[2], o[3], hv1, lv1);
    hhu[lane * 2] = hv0; hhu[lane * 2 + 1] = hv1;
    hlu[lane * 2] = lv0; hlu[lane * 2 + 1] = lv1;
    bsplit(o[4], o[5], hv0, lv0); bsplit(o[6], o[7], hv1, lv1);
    hhu[64 + lane * 2] = hv0; hhu[64 + lane * 2 + 1] = hv1;
    hlu[64 + lane * 2] = lv0; hlu[64 + lane * 2 + 1] = lv1;
}

// ---------------- host ----------------
static GProb mkprob(const ushortx* ah0, const ushortx* al0,
                    const ushortx* ah1, const ushortx* al1,
                    const ushortx* ah2, const ushortx* al2,
                    const ushortx* Bh, const ushortx* Bl,
                    const float* bias, float* C, ushortx* Ch, ushortx* Cl,
                    int M, int Ktot, int Kseg, int relu) {
    GProb p;
    p.ah0 = ah0; p.al0 = al0; p.ah1 = ah1; p.al1 = al1; p.ah2 = ah2; p.al2 = al2;
    p.Bh = Bh; p.Bl = Bl; p.bias = bias; p.C = C; p.Ch = Ch; p.Cl = Cl;
    p.M = M; p.Ktot = Ktot; p.Kseg = Kseg; p.relu = relu;
    return p;
}
static inline void bgemm2(const GProb& p0, const GProb& p1, int nz) {
    int my = (p0.M + 127) >> 7;
    if (nz == 2) { int m1 = (p1.M + 127) >> 7; if (m1 > my) my = m1; }
    dim3 grid(2, my, nz);
    k_bgemm<<<grid, 256, NSTAGE * STAGE>>>(p0, p1);
}

extern "C" void kernel_launch(void* const* d_in, const int* in_sizes, int n_in,
                              void* d_out, int out_size) {
    const float* x_author     = (const float*)d_in[0];
    const float* x_paper      = (const float*)d_in[1];
    const int*   e0_src       = (const int*)d_in[2];
    const int*   e0_dst       = (const int*)d_in[3];
    const int*   e1_src       = (const int*)d_in[4];
    const int*   e1_dst       = (const int*)d_in[5];
    const int*   e2_src       = (const int*)d_in[6];
    const int*   e2_dst       = (const int*)d_in[7];
    const float* emb_W_author = (const float*)d_in[8];
    const float* emb_b_author = (const float*)d_in[9];
    const float* emb_W_paper  = (const float*)d_in[10];
    const float* emb_b_paper  = (const float*)d_in[11];
    const float* W_self       = (const float*)d_in[12];
    const float* W_neigh      = (const float*)d_in[13];
    const float* b_conv       = (const float*)d_in[14];
    const float* ln_g_author  = (const float*)d_in[15];
    const float* ln_b_author  = (const float*)d_in[16];
    const float* ln_g_paper   = (const float*)d_in[17];
    const float* ln_b_paper   = (const float*)d_in[18];
    const float* pW1_author   = (const float*)d_in[19];
    const float* pb1_author   = (const float*)d_in[20];
    const float* pW2_author   = (const float*)d_in[21];
    const float* pb2_author   = (const float*)d_in[22];
    const float* pW1_paper    = (const float*)d_in[23];
    const float* pb1_paper    = (const float*)d_in[24];
    const float* pW2_paper    = (const float*)d_in[25];
    const float* pb2_paper    = (const float*)d_in[26];

    cudaFuncSetAttribute(k_bgemm, cudaFuncAttributeMaxDynamicSharedMemorySize, NSTAGE * STAGE);

    float *p_ta, *p_tp, *p_b01;
    ushortx *p_xah, *p_xal, *p_xph, *p_xpl, *p_hah, *p_hal, *p_hph, *p_hpl;
    ushortx *p_ag0h, *p_ag0l, *p_ag1h, *p_ag1l, *p_ag2h, *p_ag2l, *p_wh, *p_wl;
    int *p_deg, *p_off, *p_cur, *p_perm, *p_part;
    cudaGetSymbolAddress((void**)&p_ta, g_ta);
    cudaGetSymbolAddress((void**)&p_tp, g_tp);
    cudaGetSymbolAddress((void**)&p_b01, g_b01);
    cudaGetSymbolAddress((void**)&p_xah, g_xah);
    cudaGetSymbolAddress((void**)&p_xal, g_xal);
    cudaGetSymbolAddress((void**)&p_xph, g_xph);
    cudaGetSymbolAddress((void**)&p_xpl, g_xpl);
    cudaGetSymbolAddress((void**)&p_hah, g_hah);
    cudaGetSymbolAddress((void**)&p_hal, g_hal);
    cudaGetSymbolAddress((void**)&p_hph, g_hph);
    cudaGetSymbolAddress((void**)&p_hpl, g_hpl);
    cudaGetSymbolAddress((void**)&p_ag0h, g_ag0h);
    cudaGetSymbolAddress((void**)&p_ag0l, g_ag0l);
    cudaGetSymbolAddress((void**)&p_ag1h, g_ag1h);
    cudaGetSymbolAddress((void**)&p_ag1l, g_ag1l);
    cudaGetSymbolAddress((void**)&p_ag2h, g_ag2h);
    cudaGetSymbolAddress((void**)&p_ag2l, g_ag2l);
    cudaGetSymbolAddress((void**)&p_wh, g_wh);
    cudaGetSymbolAddress((void**)&p_wl, g_wl);
    cudaGetSymbolAddress((void**)&p_deg, g_deg);
    cudaGetSymbolAddress((void**)&p_off, g_off);
    cudaGetSymbolAddress((void**)&p_cur, g_cur);
    cudaGetSymbolAddress((void**)&p_perm, g_perm);
    cudaGetSymbolAddress((void**)&p_part, g_part);

    // ---- splits + bias combine + deg zeroing in ONE vectorized launch ----
    k_split_all<<<(NS4 + 255) / 256, 256>>>(
        x_author, x_paper, emb_W_author, emb_W_paper, W_self, W_neigh,
        pW1_author, pW1_paper, pW2_paper, b_conv,
        p_wh, p_wl, p_xah, p_xal, p_xph, p_xpl, p_b01, p_deg);

    // ---- CSR build ----
    k_hist3<<<(3 * EN + 255) / 256, 256>>>(e0_dst, e1_dst, e2_dst, p_deg);
    k_scan_sum<<<NBT, 1024>>>(p_deg, p_part);
    k_scan_top<<<1, 96>>>(p_part, p_off);
    k_scan_apply<<<NBT, 1024>>>(p_deg, p_part, p_off, p_cur);
    k_fill3<<<(3 * EN + 255) / 256, 256>>>(e0_src, e0_dst, e1_src, e1_dst,
                                           e2_src, e2_dst, p_cur, p_perm);

    // ---- embeddings ----
    bgemm2(mkprob(p_xah, p_xal, 0, 0, 0, 0, p_wh + WOFF_EMBA, p_wl + WOFF_EMBA,
                  emb_b_author, 0, p_hah, p_hal, AN, DIN, DIN, 0),
           mkprob(p_xph, p_xpl, 0, 0, 0, 0, p_wh + WOFF_EMBP, p_wl + WOFF_EMBP,
                  emb_b_paper, 0, p_hph, p_hpl, PN, DIN, DIN, 0), 2);

    // ---- 2 SAGE layers ----
    const int WPO[2] = {WOFF_WP0, WOFF_WP1};
    const int WAO[2] = {WOFF_WA0, WOFF_WA1};
    const int NWARP_AGG = 2 * PN + AN;
    for (int l = 0; l < 2; ++l) {
        const float* bc = b_conv + (size_t)l * 3 * HD;
        k_agg3<<<(NWARP_AGG * 32 + 127) / 128, 128>>>(
            p_hah, p_hal, p_hph, p_hpl, p_off, p_perm,
            p_ag0h, p_ag0l, p_ag1h, p_ag1l, p_ag2h, p_ag2l);
        bgemm2(mkprob(p_hph, p_hpl, p_ag0h, p_ag0l, p_ag1h, p_ag1l,
                      p_wh + WPO[l], p_wl + WPO[l], p_b01 + l * HD,
                      p_tp, 0, 0, PN, 3 * HD, HD, 0),
               mkprob(p_hah, p_hal, p_ag2h, p_ag2l, 0, 0,
                      p_wh + WAO[l], p_wl + WAO[l], bc + 2 * HD,
                      p_ta, 0, 0, AN, 2 * HD, HD, 0), 2);
        k_ln2<<<((AN + PN) * 32 + 127) / 128, 128>>>(
            p_ta, p_hah, p_hal, ln_g_author, ln_b_author,
            p_tp, p_hph, p_hpl, ln_g_paper, ln_b_paper);
    }

    // ---- output heads ----
    float* out = (float*)d_out;
    bgemm2(mkprob(p_hah, p_hal, 0, 0, 0, 0, p_wh + WOFF_P1A, p_wl + WOFF_P1A,
                  pb1_author, p_ta, 0, 0, AN, HD, HD, 1),
           mkprob(p_hph, p_hpl, 0, 0, 0, 0, p_wh + WOFF_P1P, p_wl + WOFF_P1P,
                  pb1_paper, 0, p_ag0h, p_ag0l, PN, HD, HD, 1), 2);
    bgemm2(mkprob(p_ag0h, p_ag0l, 0, 0, 0, 0, p_wh + WOFF_P2P, p_wl + WOFF_P2P,
                  pb2_paper, out + (size_t)AN * CN, 0, 0, PN, HD, HD, 0),
           mkprob(0, 0, 0, 0, 0, 0, 0, 0, 0, 0, 0, 0, 0, HD, HD, 0), 1);
    {
        dim3 grid((CN + BN - 1) / BN, (AN + BM - 1) / BM);
        k_sgemm_lsm<<<grid, 256>>>(p_ta, pW2_author, pb2_author, out, AN, CN, HD);
    }
}